// round 2
// baseline (speedup 1.0000x reference)
#include <cuda_runtime.h>
#include <cstdint>

// Problem constants
#define Bc   128
#define Cc   64
#define Hc   32
#define Wc   32
#define NEDGE 6

#define PLANE   (Hc*Wc)                // 1024
#define IMGSZ   (Cc*PLANE)             // 65536
#define TOTSZ   (Bc*IMGSZ)             // 8388608
#define WSZ     (NEDGE*Cc*Cc*9)        // 2359296

// ---------------- device scratch (no allocs allowed) ----------------
__device__ float d_r0[TOTSZ];
__device__ float d_r1[TOTSZ];
__device__ float d_r2[TOTSZ];
__device__ float d_acc2[TOTSZ];
__device__ float d_acc3[TOTSZ];
__device__ float d_Wt[NEDGE*9*Cc*Cc];   // [l][s][ci][oc]
__device__ float d_ain[Cc];
__device__ float d_aout[Cc];

// ---------------- K0: cumulative channel scales ----------------
__global__ void scales_kernel(const float* __restrict__ a1,
                              const float* __restrict__ a2) {
    int c = threadIdx.x;
    if (c < Cc) {
        float s1 = 0.f, s2 = 0.f;
        #pragma unroll
        for (int i = 0; i < 8; i++) {
            if (c < 8*(i+1)) { s1 += a1[i]; s2 += a2[i]; }
        }
        d_ain[c]  = s1;
        d_aout[c] = s2;
    }
}

// ---------------- K1: weight transpose OIHW -> [l][s][ci][oc] ----------------
__global__ void transpose_w_kernel(const float* __restrict__ W) {
    int idx = blockIdx.x * 256 + threadIdx.x;
    if (idx >= NEDGE*9*Cc*Cc) return;
    int oc = idx & 63;
    int t  = idx >> 6;
    int ci = t & 63;  t >>= 6;
    int s  = t % 9;
    int l  = t / 9;
    d_Wt[idx] = W[(((l*Cc + oc)*Cc + ci)*9) + s];
}

// ---------------- K2: r0 = a_in * relu(x) ----------------
__global__ void prescale_kernel(const float* __restrict__ x) {
    int i = blockIdx.x * blockDim.x + threadIdx.x;     // float4 index
    const int NV = TOTSZ / 4;
    if (i >= NV) return;
    int c = (i >> 8) & 63;                             // 256 float4 per (b,c) plane
    float a = d_ain[c];
    float4 v = ((const float4*)x)[i];
    v.x = a * fmaxf(v.x, 0.f);
    v.y = a * fmaxf(v.y, 0.f);
    v.z = a * fmaxf(v.z, 0.f);
    v.w = a * fmaxf(v.w, 0.f);
    ((float4*)d_r0)[i] = v;
}

// ---------------- conv pass ----------------
// mode 0: out = conv + (addin ? addin : 0)            (plain accumulate)
// mode 1: out = a_in * relu(a_out * (conv + addin))   (produce next node's r)
// mode 2: out = a_out * (conv + addin)                (final node output)
struct EdgeSpec {
    int l;
    int mode;
    const float* addin;  // may be null
    float* out;
};

// block: (band 0..3, batch 0..127, edge), 256 threads
// thread: ocg = tid>>5 (8 oc), lane: r = lane>>2 (row in band), wg = lane&3 (8 cols)
__global__ __launch_bounds__(256, 2)
void conv_pass_kernel(const float* __restrict__ in,
                      EdgeSpec e0, EdgeSpec e1, EdgeSpec e2) {
    __shared__ float s_in[8][10][35];      // [ci_chunk][row(-1..+8)][col(-1..32) pad]
    __shared__ float s_wt[9][8][Cc];       // [s][ci_chunk][oc]

    EdgeSpec spec = (blockIdx.z == 0) ? e0 : (blockIdx.z == 1) ? e1 : e2;

    const int band = blockIdx.x;
    const int b    = blockIdx.y;
    const int tid  = threadIdx.x;
    const int ocg  = tid >> 5;
    const int lane = tid & 31;
    const int r    = lane >> 2;
    const int wg   = lane & 3;
    const int row0 = band * 8;

    float acc[8][8];   // [col j][oc o]
    #pragma unroll
    for (int j = 0; j < 8; j++)
        #pragma unroll
        for (int o = 0; o < 8; o++) acc[j][o] = 0.f;

    const float* wbase = d_Wt + (size_t)spec.l * 9 * Cc * Cc;
    const float* inb   = in + (size_t)b * IMGSZ;

    for (int chunk = 0; chunk < 8; chunk++) {
        __syncthreads();
        // ---- load input chunk: 8 ci x 10 rows x 34 cols ----
        for (int idx = tid; idx < 8*10*34; idx += 256) {
            int cc  = idx / 340;
            int rem = idx - cc * 340;
            int rr  = rem / 34;
            int cw  = rem - rr * 34;
            int gr  = row0 - 1 + rr;
            int w   = cw - 1;
            float v = 0.f;
            if ((unsigned)gr < 32u && (unsigned)w < 32u)
                v = inb[((chunk*8 + cc) * Hc + gr) * Wc + w];
            s_in[cc][rr][cw] = v;
        }
        // ---- load weight chunk: 9 s x 8 ci x 64 oc (coalesced) ----
        for (int idx = tid; idx < 9*8*64; idx += 256) {
            int s   = idx >> 9;
            int rem = idx & 511;
            int cc  = rem >> 6;
            int oc  = rem & 63;
            s_wt[s][cc][oc] = wbase[(s*Cc + chunk*8 + cc)*Cc + oc];
        }
        __syncthreads();

        // ---- compute ----
        #pragma unroll 1
        for (int cc = 0; cc < 8; cc++) {
            #pragma unroll
            for (int ky = 0; ky < 3; ky++) {
                float inv[10];
                #pragma unroll
                for (int j = 0; j < 10; j++)
                    inv[j] = s_in[cc][r + ky][wg*8 + j];
                #pragma unroll
                for (int kx = 0; kx < 3; kx++) {
                    const float4 w0 = *(const float4*)&s_wt[ky*3 + kx][cc][ocg*8];
                    const float4 w1 = *(const float4*)&s_wt[ky*3 + kx][cc][ocg*8 + 4];
                    #pragma unroll
                    for (int j = 0; j < 8; j++) {
                        float iv = inv[j + kx];
                        acc[j][0] += iv * w0.x;
                        acc[j][1] += iv * w0.y;
                        acc[j][2] += iv * w0.z;
                        acc[j][3] += iv * w0.w;
                        acc[j][4] += iv * w1.x;
                        acc[j][5] += iv * w1.y;
                        acc[j][6] += iv * w1.z;
                        acc[j][7] += iv * w1.w;
                    }
                }
            }
        }
    }

    // ---- epilogue ----
    const int row  = row0 + r;
    const int col0 = wg * 8;
    const int mode = spec.mode;
    #pragma unroll
    for (int o = 0; o < 8; o++) {
        int oc = ocg * 8 + o;
        float ai = d_ain[oc];
        float ao = d_aout[oc];
        size_t base = (((size_t)b * Cc + oc) * Hc + row) * Wc + col0;
        float v[8];
        #pragma unroll
        for (int j = 0; j < 8; j++) v[j] = acc[j][o];
        if (spec.addin) {
            float4 A0 = *(const float4*)(spec.addin + base);
            float4 A1 = *(const float4*)(spec.addin + base + 4);
            v[0] += A0.x; v[1] += A0.y; v[2] += A0.z; v[3] += A0.w;
            v[4] += A1.x; v[5] += A1.y; v[6] += A1.z; v[7] += A1.w;
        }
        if (mode == 1) {
            #pragma unroll
            for (int j = 0; j < 8; j++) v[j] = ai * fmaxf(ao * v[j], 0.f);
        } else if (mode == 2) {
            #pragma unroll
            for (int j = 0; j < 8; j++) v[j] *= ao;
        }
        *(float4*)(spec.out + base)     = make_float4(v[0], v[1], v[2], v[3]);
        *(float4*)(spec.out + base + 4) = make_float4(v[4], v[5], v[6], v[7]);
    }
}

// ---------------- launch ----------------
extern "C" void kernel_launch(void* const* d_in, const int* in_sizes, int n_in,
                              void* d_out, int out_size) {
    // Identify inputs robustly by size: inputs(8388608), alphas1(8), alphas2(8), W(2359296)
    const float* x  = nullptr;
    const float* a1 = nullptr;
    const float* a2 = nullptr;
    const float* W  = nullptr;
    for (int i = 0; i < n_in; i++) {
        if (in_sizes[i] == TOTSZ)      x = (const float*)d_in[i];
        else if (in_sizes[i] == WSZ)   W = (const float*)d_in[i];
        else if (in_sizes[i] == 8) {
            if (!a1) a1 = (const float*)d_in[i];
            else     a2 = (const float*)d_in[i];
        }
    }
    float* out = (float*)d_out;

    float *r0, *r1, *r2, *acc2, *acc3;
    cudaGetSymbolAddress((void**)&r0,   d_r0);
    cudaGetSymbolAddress((void**)&r1,   d_r1);
    cudaGetSymbolAddress((void**)&r2,   d_r2);
    cudaGetSymbolAddress((void**)&acc2, d_acc2);
    cudaGetSymbolAddress((void**)&acc3, d_acc3);

    scales_kernel<<<1, 64>>>(a1, a2);
    transpose_w_kernel<<<(NEDGE*9*Cc*Cc + 255)/256, 256>>>(W);
    prescale_kernel<<<(TOTSZ/4 + 255)/256, 256>>>(x);

    // Pass A: from r0 -> {r1 (W0), acc2 (W1), acc3 (W3)}
    EdgeSpec eA0{0, 1, nullptr, r1};
    EdgeSpec eA1{1, 0, nullptr, acc2};
    EdgeSpec eA2{3, 0, nullptr, acc3};
    conv_pass_kernel<<<dim3(4, Bc, 3), 256>>>(r0, eA0, eA1, eA2);

    // Pass B: from r1 -> {r2 (W2 + acc2), acc3 += W4}
    EdgeSpec eB0{2, 1, acc2, r2};
    EdgeSpec eB1{4, 0, acc3, acc3};
    conv_pass_kernel<<<dim3(4, Bc, 2), 256>>>(r1, eB0, eB1, eB1);

    // Pass C: out = a_out * (acc3 + conv(r2, W5))
    EdgeSpec eC0{5, 2, acc3, out};
    conv_pass_kernel<<<dim3(4, Bc, 1), 256>>>(r2, eC0, eC0, eC0);

    (void)out_size;
}

// round 3
// speedup vs baseline: 1.1427x; 1.1427x over previous
#include <cuda_runtime.h>
#include <cstdint>

// Problem constants
#define Bc   128
#define Cc   64
#define Hc   32
#define Wc   32
#define NEDGE 6

#define PLANE   (Hc*Wc)                // 1024
#define IMGSZ   (Cc*PLANE)             // 65536
#define TOTSZ   (Bc*IMGSZ)             // 8388608
#define WSZ     (NEDGE*Cc*Cc*9)        // 2359296

typedef unsigned long long u64;

// ---------------- device scratch (no allocs allowed) ----------------
__device__ float d_r0[TOTSZ];
__device__ float d_r1[TOTSZ];
__device__ float d_r2[TOTSZ];
__device__ float d_acc2[TOTSZ];
__device__ float d_acc3[TOTSZ];
__device__ float d_Wt[NEDGE*9*Cc*Cc];   // [l][s][ci][oc]
__device__ float d_ain[Cc];
__device__ float d_aout[Cc];

// ---------------- packed fp32x2 helpers (sm_103a FFMA2) ----------------
__device__ __forceinline__ void ffma2(u64& acc, u64 a, u64 b) {
    asm("fma.rn.f32x2 %0, %1, %2, %0;" : "+l"(acc) : "l"(a), "l"(b));
}
__device__ __forceinline__ u64 dup2(float v) {
    u64 r;
    asm("mov.b64 %0, {%1, %1};" : "=l"(r) : "f"(v));
    return r;
}
__device__ __forceinline__ void unpack2(u64 v, float& lo, float& hi) {
    asm("mov.b64 {%0, %1}, %2;" : "=f"(lo), "=f"(hi) : "l"(v));
}

// ---------------- K0: cumulative channel scales ----------------
__global__ void scales_kernel(const float* __restrict__ a1,
                              const float* __restrict__ a2) {
    int c = threadIdx.x;
    if (c < Cc) {
        float s1 = 0.f, s2 = 0.f;
        #pragma unroll
        for (int i = 0; i < 8; i++) {
            if (c < 8*(i+1)) { s1 += a1[i]; s2 += a2[i]; }
        }
        d_ain[c]  = s1;
        d_aout[c] = s2;
    }
}

// ---------------- K1: weight transpose OIHW -> [l][s][ci][oc] ----------------
__global__ void transpose_w_kernel(const float* __restrict__ W) {
    int idx = blockIdx.x * 256 + threadIdx.x;
    if (idx >= NEDGE*9*Cc*Cc) return;
    int oc = idx & 63;
    int t  = idx >> 6;
    int ci = t & 63;  t >>= 6;
    int s  = t % 9;
    int l  = t / 9;
    d_Wt[idx] = W[(((l*Cc + oc)*Cc + ci)*9) + s];
}

// ---------------- K2: r0 = a_in * relu(x) ----------------
__global__ void prescale_kernel(const float* __restrict__ x) {
    int i = blockIdx.x * blockDim.x + threadIdx.x;     // float4 index
    const int NV = TOTSZ / 4;
    if (i >= NV) return;
    int c = (i >> 8) & 63;                             // 256 float4 per (b,c) plane
    float a = d_ain[c];
    float4 v = ((const float4*)x)[i];
    v.x = a * fmaxf(v.x, 0.f);
    v.y = a * fmaxf(v.y, 0.f);
    v.z = a * fmaxf(v.z, 0.f);
    v.w = a * fmaxf(v.w, 0.f);
    ((float4*)d_r0)[i] = v;
}

// ---------------- conv pass ----------------
// mode 0: out = conv + (addin ? addin : 0)            (plain accumulate)
// mode 1: out = a_in * relu(a_out * (conv + addin))   (produce next node's r)
// mode 2: out = a_out * (conv + addin)                (final node output)
struct EdgeSpec {
    int l;
    int mode;
    const float* addin;  // may be null
    float* out;
};

// block: (band 0..3, batch 0..127, edge), 256 threads
// thread: ocg = tid>>5 (8 oc), lane: r = lane>>2 (row in band), wg = lane&3 (8 cols)
__global__ __launch_bounds__(256, 2)
void conv_pass_kernel(const float* __restrict__ in,
                      EdgeSpec e0, EdgeSpec e1, EdgeSpec e2) {
    __shared__ float s_in[8][10][35];      // [ci_chunk][row(-1..+8)][col(-1..32) pad]
    __shared__ float s_wt[9][8][Cc];       // [s][ci_chunk][oc]

    EdgeSpec spec = (blockIdx.z == 0) ? e0 : (blockIdx.z == 1) ? e1 : e2;

    const int band = blockIdx.x;
    const int b    = blockIdx.y;
    const int tid  = threadIdx.x;
    const int ocg  = tid >> 5;
    const int lane = tid & 31;
    const int r    = lane >> 2;
    const int wg   = lane & 3;
    const int row0 = band * 8;

    // acc[j][p] packs output channels (ocg*8 + 2p, ocg*8 + 2p + 1) as f32x2
    u64 acc[8][4];
    #pragma unroll
    for (int j = 0; j < 8; j++)
        #pragma unroll
        for (int p = 0; p < 4; p++) acc[j][p] = 0ull;

    const float* wbase = d_Wt + (size_t)spec.l * 9 * Cc * Cc;
    const float* inb   = in + (size_t)b * IMGSZ;

    for (int chunk = 0; chunk < 8; chunk++) {
        __syncthreads();
        // ---- load input chunk: 8 ci x 10 rows x 34 cols ----
        for (int idx = tid; idx < 8*10*34; idx += 256) {
            int cc  = idx / 340;
            int rem = idx - cc * 340;
            int rr  = rem / 34;
            int cw  = rem - rr * 34;
            int gr  = row0 - 1 + rr;
            int w   = cw - 1;
            float v = 0.f;
            if ((unsigned)gr < 32u && (unsigned)w < 32u)
                v = inb[((chunk*8 + cc) * Hc + gr) * Wc + w];
            s_in[cc][rr][cw] = v;
        }
        // ---- load weight chunk: 9 s x 8 ci x 64 oc (coalesced) ----
        for (int idx = tid; idx < 9*8*64; idx += 256) {
            int s   = idx >> 9;
            int rem = idx & 511;
            int cc  = rem >> 6;
            int oc  = rem & 63;
            s_wt[s][cc][oc] = wbase[(s*Cc + chunk*8 + cc)*Cc + oc];
        }
        __syncthreads();

        // ---- compute: packed f32x2 FMA over output-channel pairs ----
        #pragma unroll 1
        for (int cc = 0; cc < 8; cc++) {
            #pragma unroll
            for (int ky = 0; ky < 3; ky++) {
                float inv[10];
                #pragma unroll
                for (int j = 0; j < 10; j++)
                    inv[j] = s_in[cc][r + ky][wg*8 + j];
                #pragma unroll
                for (int kx = 0; kx < 3; kx++) {
                    // weight pairs: consecutive floats in smem == f32x2 operands
                    const ulonglong2 wA = *(const ulonglong2*)&s_wt[ky*3 + kx][cc][ocg*8];
                    const ulonglong2 wB = *(const ulonglong2*)&s_wt[ky*3 + kx][cc][ocg*8 + 4];
                    #pragma unroll
                    for (int j = 0; j < 8; j++) {
                        u64 iv = dup2(inv[j + kx]);
                        ffma2(acc[j][0], iv, wA.x);
                        ffma2(acc[j][1], iv, wA.y);
                        ffma2(acc[j][2], iv, wB.x);
                        ffma2(acc[j][3], iv, wB.y);
                    }
                }
            }
        }
    }

    // ---- epilogue ----
    const int row  = row0 + r;
    const int col0 = wg * 8;
    const int mode = spec.mode;
    #pragma unroll
    for (int p = 0; p < 4; p++) {
        float va[8], vb[8];
        #pragma unroll
        for (int j = 0; j < 8; j++)
            unpack2(acc[j][p], va[j], vb[j]);

        #pragma unroll
        for (int half = 0; half < 2; half++) {
            float* v = half ? vb : va;
            int oc = ocg * 8 + 2*p + half;
            float ai = d_ain[oc];
            float ao = d_aout[oc];
            size_t base = (((size_t)b * Cc + oc) * Hc + row) * Wc + col0;
            if (spec.addin) {
                float4 A0 = *(const float4*)(spec.addin + base);
                float4 A1 = *(const float4*)(spec.addin + base + 4);
                v[0] += A0.x; v[1] += A0.y; v[2] += A0.z; v[3] += A0.w;
                v[4] += A1.x; v[5] += A1.y; v[6] += A1.z; v[7] += A1.w;
            }
            if (mode == 1) {
                #pragma unroll
                for (int j = 0; j < 8; j++) v[j] = ai * fmaxf(ao * v[j], 0.f);
            } else if (mode == 2) {
                #pragma unroll
                for (int j = 0; j < 8; j++) v[j] *= ao;
            }
            *(float4*)(spec.out + base)     = make_float4(v[0], v[1], v[2], v[3]);
            *(float4*)(spec.out + base + 4) = make_float4(v[4], v[5], v[6], v[7]);
        }
    }
}

// ---------------- launch ----------------
extern "C" void kernel_launch(void* const* d_in, const int* in_sizes, int n_in,
                              void* d_out, int out_size) {
    // Identify inputs robustly by size: inputs(8388608), alphas1(8), alphas2(8), W(2359296)
    const float* x  = nullptr;
    const float* a1 = nullptr;
    const float* a2 = nullptr;
    const float* W  = nullptr;
    for (int i = 0; i < n_in; i++) {
        if (in_sizes[i] == TOTSZ)      x = (const float*)d_in[i];
        else if (in_sizes[i] == WSZ)   W = (const float*)d_in[i];
        else if (in_sizes[i] == 8) {
            if (!a1) a1 = (const float*)d_in[i];
            else     a2 = (const float*)d_in[i];
        }
    }
    float* out = (float*)d_out;

    float *r0, *r1, *r2, *acc2, *acc3;
    cudaGetSymbolAddress((void**)&r0,   d_r0);
    cudaGetSymbolAddress((void**)&r1,   d_r1);
    cudaGetSymbolAddress((void**)&r2,   d_r2);
    cudaGetSymbolAddress((void**)&acc2, d_acc2);
    cudaGetSymbolAddress((void**)&acc3, d_acc3);

    scales_kernel<<<1, 64>>>(a1, a2);
    transpose_w_kernel<<<(NEDGE*9*Cc*Cc + 255)/256, 256>>>(W);
    prescale_kernel<<<(TOTSZ/4 + 255)/256, 256>>>(x);

    // Pass A: from r0 -> {r1 (W0), acc2 (W1), acc3 (W3)}
    EdgeSpec eA0{0, 1, nullptr, r1};
    EdgeSpec eA1{1, 0, nullptr, acc2};
    EdgeSpec eA2{3, 0, nullptr, acc3};
    conv_pass_kernel<<<dim3(4, Bc, 3), 256>>>(r0, eA0, eA1, eA2);

    // Pass B: from r1 -> {r2 (W2 + acc2), acc3 += W4}
    EdgeSpec eB0{2, 1, acc2, r2};
    EdgeSpec eB1{4, 0, acc3, acc3};
    conv_pass_kernel<<<dim3(4, Bc, 2), 256>>>(r1, eB0, eB1, eB1);

    // Pass C: out = a_out * (acc3 + conv(r2, W5))
    EdgeSpec eC0{5, 2, acc3, out};
    conv_pass_kernel<<<dim3(4, Bc, 1), 256>>>(r2, eC0, eC0, eC0);

    (void)out_size;
}

// round 4
// speedup vs baseline: 1.1448x; 1.0018x over previous
#include <cuda_runtime.h>
#include <cstdint>

// Problem constants
#define Bc   128
#define Cc   64
#define Hc   32
#define Wc   32
#define NEDGE 6

#define PLANE   (Hc*Wc)                // 1024
#define IMGSZ   (Cc*PLANE)             // 65536
#define TOTSZ   (Bc*IMGSZ)             // 8388608
#define WSZ     (NEDGE*Cc*Cc*9)        // 2359296

typedef unsigned long long u64;

// ---------------- device scratch (no allocs allowed) ----------------
__device__ float d_r0[TOTSZ];
__device__ float d_r1[TOTSZ];
__device__ float d_r2[TOTSZ];
__device__ float d_acc2[TOTSZ];
__device__ float d_acc3[TOTSZ];
__device__ float d_Wt[NEDGE*9*Cc*Cc];   // [l][s][ci][oc]
__device__ float d_ain[Cc];
__device__ float d_aout[Cc];

// ---------------- packed fp32x2 helpers (sm_103a FFMA2) ----------------
__device__ __forceinline__ void ffma2(u64& acc, u64 a, u64 b) {
    asm("fma.rn.f32x2 %0, %1, %2, %0;" : "+l"(acc) : "l"(a), "l"(b));
}
__device__ __forceinline__ u64 dup2(float v) {
    u64 r;
    asm("mov.b64 %0, {%1, %1};" : "=l"(r) : "f"(v));
    return r;
}
__device__ __forceinline__ void unpack2(u64 v, float& lo, float& hi) {
    asm("mov.b64 {%0, %1}, %2;" : "=f"(lo), "=f"(hi) : "l"(v));
}

// ---------------- K0: cumulative channel scales ----------------
__global__ void scales_kernel(const float* __restrict__ a1,
                              const float* __restrict__ a2) {
    int c = threadIdx.x;
    if (c < Cc) {
        float s1 = 0.f, s2 = 0.f;
        #pragma unroll
        for (int i = 0; i < 8; i++) {
            if (c < 8*(i+1)) { s1 += a1[i]; s2 += a2[i]; }
        }
        d_ain[c]  = s1;
        d_aout[c] = s2;
    }
}

// ---------------- K1: weight transpose OIHW -> [l][s][ci][oc] ----------------
__global__ void transpose_w_kernel(const float* __restrict__ W) {
    int idx = blockIdx.x * 256 + threadIdx.x;
    if (idx >= NEDGE*9*Cc*Cc) return;
    int oc = idx & 63;
    int t  = idx >> 6;
    int ci = t & 63;  t >>= 6;
    int s  = t % 9;
    int l  = t / 9;
    d_Wt[idx] = W[(((l*Cc + oc)*Cc + ci)*9) + s];
}

// ---------------- K2: r0 = a_in * relu(x) ----------------
__global__ void prescale_kernel(const float* __restrict__ x) {
    int i = blockIdx.x * blockDim.x + threadIdx.x;     // float4 index
    const int NV = TOTSZ / 4;
    if (i >= NV) return;
    int c = (i >> 8) & 63;                             // 256 float4 per (b,c) plane
    float a = d_ain[c];
    float4 v = ((const float4*)x)[i];
    v.x = a * fmaxf(v.x, 0.f);
    v.y = a * fmaxf(v.y, 0.f);
    v.z = a * fmaxf(v.z, 0.f);
    v.w = a * fmaxf(v.w, 0.f);
    ((float4*)d_r0)[i] = v;
}

// ---------------- conv pass ----------------
// mode 0: out = conv + (addin ? addin : 0)            (plain accumulate)
// mode 1: out = a_in * relu(a_out * (conv + addin))   (produce next node's r)
// mode 2: out = a_out * (conv + addin)                (final node output)
struct EdgeSpec {
    int l;
    int mode;
    const float* addin;  // may be null
    float* out;
};

// block: (band 0..3, batch 0..127, edge), 256 threads
// thread: ocg = tid>>5 (8 oc), lane: r = lane>>2 (row in band), wg = lane&3 (8 cols)
__global__ __launch_bounds__(256, 2)
void conv_pass_kernel(const float* __restrict__ in,
                      EdgeSpec e0, EdgeSpec e1, EdgeSpec e2) {
    __shared__ float s_in[8][10][35];      // [ci_chunk][row(-1..+8)][col(-1..32) pad]
    __shared__ float s_wt[9][8][Cc];       // [s][ci_chunk][oc]

    EdgeSpec spec = (blockIdx.z == 0) ? e0 : (blockIdx.z == 1) ? e1 : e2;

    const int band = blockIdx.x;
    const int b    = blockIdx.y;
    const int tid  = threadIdx.x;
    const int ocg  = tid >> 5;
    const int lane = tid & 31;
    const int r    = lane >> 2;
    const int wg   = lane & 3;
    const int row0 = band * 8;

    // acc[j][p] packs output channels (ocg*8 + 2p, ocg*8 + 2p + 1) as f32x2
    u64 acc[8][4];
    #pragma unroll
    for (int j = 0; j < 8; j++)
        #pragma unroll
        for (int p = 0; p < 4; p++) acc[j][p] = 0ull;

    const float* wbase = d_Wt + (size_t)spec.l * 9 * Cc * Cc;
    const float* inb   = in + (size_t)b * IMGSZ;

    for (int chunk = 0; chunk < 8; chunk++) {
        __syncthreads();
        // ---- load input chunk: 8 ci x 10 rows x 34 cols ----
        for (int idx = tid; idx < 8*10*34; idx += 256) {
            int cc  = idx / 340;
            int rem = idx - cc * 340;
            int rr  = rem / 34;
            int cw  = rem - rr * 34;
            int gr  = row0 - 1 + rr;
            int w   = cw - 1;
            float v = 0.f;
            if ((unsigned)gr < 32u && (unsigned)w < 32u)
                v = inb[((chunk*8 + cc) * Hc + gr) * Wc + w];
            s_in[cc][rr][cw] = v;
        }
        // ---- load weight chunk: 9 s x 8 ci x 64 oc (coalesced) ----
        for (int idx = tid; idx < 9*8*64; idx += 256) {
            int s   = idx >> 9;
            int rem = idx & 511;
            int cc  = rem >> 6;
            int oc  = rem & 63;
            s_wt[s][cc][oc] = wbase[(s*Cc + chunk*8 + cc)*Cc + oc];
        }
        __syncthreads();

        // ---- compute: packed f32x2 FMA over output-channel pairs ----
        #pragma unroll 1
        for (int cc = 0; cc < 8; cc++) {
            #pragma unroll
            for (int ky = 0; ky < 3; ky++) {
                float inv[10];
                #pragma unroll
                for (int j = 0; j < 10; j++)
                    inv[j] = s_in[cc][r + ky][wg*8 + j];
                #pragma unroll
                for (int kx = 0; kx < 3; kx++) {
                    // weight pairs: consecutive floats in smem == f32x2 operands
                    const ulonglong2 wA = *(const ulonglong2*)&s_wt[ky*3 + kx][cc][ocg*8];
                    const ulonglong2 wB = *(const ulonglong2*)&s_wt[ky*3 + kx][cc][ocg*8 + 4];
                    #pragma unroll
                    for (int j = 0; j < 8; j++) {
                        u64 iv = dup2(inv[j + kx]);
                        ffma2(acc[j][0], iv, wA.x);
                        ffma2(acc[j][1], iv, wA.y);
                        ffma2(acc[j][2], iv, wB.x);
                        ffma2(acc[j][3], iv, wB.y);
                    }
                }
            }
        }
    }

    // ---- epilogue ----
    const int row  = row0 + r;
    const int col0 = wg * 8;
    const int mode = spec.mode;
    #pragma unroll
    for (int p = 0; p < 4; p++) {
        float va[8], vb[8];
        #pragma unroll
        for (int j = 0; j < 8; j++)
            unpack2(acc[j][p], va[j], vb[j]);

        #pragma unroll
        for (int half = 0; half < 2; half++) {
            float* v = half ? vb : va;
            int oc = ocg * 8 + 2*p + half;
            float ai = d_ain[oc];
            float ao = d_aout[oc];
            size_t base = (((size_t)b * Cc + oc) * Hc + row) * Wc + col0;
            if (spec.addin) {
                float4 A0 = *(const float4*)(spec.addin + base);
                float4 A1 = *(const float4*)(spec.addin + base + 4);
                v[0] += A0.x; v[1] += A0.y; v[2] += A0.z; v[3] += A0.w;
                v[4] += A1.x; v[5] += A1.y; v[6] += A1.z; v[7] += A1.w;
            }
            if (mode == 1) {
                #pragma unroll
                for (int j = 0; j < 8; j++) v[j] = ai * fmaxf(ao * v[j], 0.f);
            } else if (mode == 2) {
                #pragma unroll
                for (int j = 0; j < 8; j++) v[j] *= ao;
            }
            *(float4*)(spec.out + base)     = make_float4(v[0], v[1], v[2], v[3]);
            *(float4*)(spec.out + base + 4) = make_float4(v[4], v[5], v[6], v[7]);
        }
    }
}

// ---------------- launch ----------------
extern "C" void kernel_launch(void* const* d_in, const int* in_sizes, int n_in,
                              void* d_out, int out_size) {
    // Identify inputs robustly by size: inputs(8388608), alphas1(8), alphas2(8), W(2359296)
    const float* x  = nullptr;
    const float* a1 = nullptr;
    const float* a2 = nullptr;
    const float* W  = nullptr;
    for (int i = 0; i < n_in; i++) {
        if (in_sizes[i] == TOTSZ)      x = (const float*)d_in[i];
        else if (in_sizes[i] == WSZ)   W = (const float*)d_in[i];
        else if (in_sizes[i] == 8) {
            if (!a1) a1 = (const float*)d_in[i];
            else     a2 = (const float*)d_in[i];
        }
    }
    float* out = (float*)d_out;

    float *r0, *r1, *r2, *acc2, *acc3;
    cudaGetSymbolAddress((void**)&r0,   d_r0);
    cudaGetSymbolAddress((void**)&r1,   d_r1);
    cudaGetSymbolAddress((void**)&r2,   d_r2);
    cudaGetSymbolAddress((void**)&acc2, d_acc2);
    cudaGetSymbolAddress((void**)&acc3, d_acc3);

    scales_kernel<<<1, 64>>>(a1, a2);
    transpose_w_kernel<<<(NEDGE*9*Cc*Cc + 255)/256, 256>>>(W);
    prescale_kernel<<<(TOTSZ/4 + 255)/256, 256>>>(x);

    // Pass A: from r0 -> {r1 (W0), acc2 (W1), acc3 (W3)}
    EdgeSpec eA0{0, 1, nullptr, r1};
    EdgeSpec eA1{1, 0, nullptr, acc2};
    EdgeSpec eA2{3, 0, nullptr, acc3};
    conv_pass_kernel<<<dim3(4, Bc, 3), 256>>>(r0, eA0, eA1, eA2);

    // Pass B: from r1 -> {r2 (W2 + acc2), acc3 += W4}
    EdgeSpec eB0{2, 1, acc2, r2};
    EdgeSpec eB1{4, 0, acc3, acc3};
    conv_pass_kernel<<<dim3(4, Bc, 2), 256>>>(r1, eB0, eB1, eB1);

    // Pass C: out = a_out * (acc3 + conv(r2, W5))
    EdgeSpec eC0{5, 2, acc3, out};
    conv_pass_kernel<<<dim3(4, Bc, 1), 256>>>(r2, eC0, eC0, eC0);

    (void)out_size;
}

// round 6
// speedup vs baseline: 2.1967x; 1.9189x over previous
#include <cuda_runtime.h>
#include <cuda_bf16.h>
#include <cstdint>

#define Bc 128
#define Cc 64
#define Hc 32
#define Wc 32
#define NEDGE 6
#define TOTSZ (Bc*Cc*Hc*Wc)
#define WSZ   (NEDGE*Cc*Cc*9)

typedef unsigned int u32;

// ---------------- device scratch ----------------
// activations: [b][h][w][128] bf16, k=0..63 hi(ci), k=64..127 lo(ci)
__device__ __align__(16) __nv_bfloat16 d_x0[TOTSZ*2];
__device__ __align__(16) __nv_bfloat16 d_x1[TOTSZ*2];
__device__ __align__(16) __nv_bfloat16 d_x2[TOTSZ*2];
__device__ float d_acc2[TOTSZ];     // NCHW fp32
__device__ float d_acc3[TOTSZ];     // NCHW fp32
// weights: [l][s][oc][128] bf16, k=0..63 hi(ci), 64..127 lo(ci)
__device__ __align__(16) __nv_bfloat16 d_wm[NEDGE*9*Cc*128];
__device__ float d_ain[Cc], d_aout[Cc];

// ---------------- PTX helpers (all baseline sm_80+ PTX) ----------------
__device__ __forceinline__ u32 smem_u32(const void* p){
    u32 a; asm("{ .reg .u64 t; cvta.to.shared.u64 t, %1; cvt.u32.u64 %0, t; }":"=r"(a):"l"(p)); return a;
}
#define CP16(dst,src) asm volatile("cp.async.ca.shared.global [%0], [%1], 16;"::"r"(dst),"l"(src):"memory")
#define CPCOMMIT()    asm volatile("cp.async.commit_group;":::"memory")
#define CPWAIT1()     asm volatile("cp.async.wait_group 1;":::"memory")
#define CPWAIT0()     asm volatile("cp.async.wait_group 0;":::"memory")

#define LDSM4(r0,r1,r2,r3,addr) \
    asm volatile("ldmatrix.sync.aligned.m8n8.x4.shared.b16 {%0,%1,%2,%3}, [%4];" \
        : "=r"(r0),"=r"(r1),"=r"(r2),"=r"(r3) : "r"(addr))

#define MMA(c,a0,a1,a2,a3,b0,b1) \
    asm volatile("mma.sync.aligned.m16n8k16.row.col.f32.bf16.bf16.f32 " \
        "{%0,%1,%2,%3},{%4,%5,%6,%7},{%8,%9},{%0,%1,%2,%3};" \
        : "+f"((c)[0]),"+f"((c)[1]),"+f"((c)[2]),"+f"((c)[3]) \
        : "r"(a0),"r"(a1),"r"(a2),"r"(a3),"r"(b0),"r"(b1))

// ---------------- prep kernels ----------------
__global__ void scales_kernel(const float* __restrict__ a1, const float* __restrict__ a2){
    int c = threadIdx.x;
    if (c < Cc){
        float s1=0.f, s2=0.f;
        #pragma unroll
        for (int i=0;i<8;i++) if (c < 8*(i+1)) { s1+=a1[i]; s2+=a2[i]; }
        d_ain[c]=s1; d_aout[c]=s2;
    }
}

// W OIHW -> [l][s][oc][128] bf16 (hi|lo)
__global__ void wprep_kernel(const float* __restrict__ W){
    int idx = blockIdx.x*256 + threadIdx.x;
    if (idx >= NEDGE*9*Cc*Cc) return;
    int ci = idx & 63, t = idx >> 6;
    int oc = t & 63; t >>= 6;
    int s = t % 9, l = t / 9;
    float w = W[(((l*Cc + oc)*Cc + ci)*9) + s];
    __nv_bfloat16 hb = __float2bfloat16(w);
    __nv_bfloat16 lb = __float2bfloat16(w - __bfloat162float(hb));
    size_t base = (size_t)((l*9 + s)*Cc + oc) * 128;
    d_wm[base + ci]      = hb;
    d_wm[base + 64 + ci] = lb;
}

// x NCHW fp32 -> d_x0 [b][h][w][128] with a_in*relu and hi/lo split
__global__ void inprep_kernel(const float* __restrict__ x){
    __shared__ float tile[Cc][Wc+1];
    int b = blockIdx.y, h = blockIdx.x, t = threadIdx.x;
    int w = t & 31, cb = t >> 5;
    #pragma unroll
    for (int i=0;i<8;i++){
        int c = cb*8 + i;
        tile[c][w] = x[(((size_t)b*Cc + c)*Hc + h)*Wc + w];
    }
    __syncthreads();
    int w2 = t >> 3, cg = (t & 7) * 8;
    u32 hi[4], lo[4];
    #pragma unroll
    for (int i=0;i<4;i++){
        int c = cg + i*2;
        float v0 = d_ain[c]   * fmaxf(tile[c][w2],   0.f);
        float v1 = d_ain[c+1] * fmaxf(tile[c+1][w2], 0.f);
        __nv_bfloat16 h0b=__float2bfloat16(v0), h1b=__float2bfloat16(v1);
        __nv_bfloat16 l0b=__float2bfloat16(v0-__bfloat162float(h0b));
        __nv_bfloat16 l1b=__float2bfloat16(v1-__bfloat162float(h1b));
        hi[i]=(u32)__bfloat16_as_ushort(h0b)|((u32)__bfloat16_as_ushort(h1b)<<16);
        lo[i]=(u32)__bfloat16_as_ushort(l0b)|((u32)__bfloat16_as_ushort(l1b)<<16);
    }
    size_t pos = ((size_t)b*Hc + h)*Wc + w2;
    *(uint4*)(d_x0 + pos*128 + cg)      = make_uint4(hi[0],hi[1],hi[2],hi[3]);
    *(uint4*)(d_x0 + pos*128 + 64 + cg) = make_uint4(lo[0],lo[1],lo[2],lo[3]);
}

// ---------------- conv pass (mma.sync bf16) ----------------
struct PassSpec {
    int l[3];
    int mode[3];            // 0: fp32 NCHW acc; 1: relu+split -> next d_x; 2: final NCHW out
    const float* addin[3];  // NCHW fp32 or null
    void* outA[3];
    const __nv_bfloat16* in;
};

// smem: input tile [204 pos][272B], then 2 weight bufs [E*64 oc][272B]
#define SM_IN_SZ (204*272)

template<int Et>
__global__ __launch_bounds__(256, 1)
void conv_mma_kernel(PassSpec ps){
    extern __shared__ __align__(16) char smem[];
    const u32 sb  = smem_u32(smem);
    const int tid = threadIdx.x;
    const int lane = tid & 31, wrp = tid >> 5;
    const int wn = wrp & 3, wm = wrp >> 2;        // 4 n-rows x 2 oc-halves
    const int band = blockIdx.x, b = blockIdx.y;
    const int h0 = band * 4;
    const int WBUF = Et*64*272;
    const u32 sbW = sb + SM_IN_SZ;

    // ---- stage input tile: 204 pos rows x 256B (+16B pad) ----
    for (int idx = tid; idx < 204*16; idx += 256){
        int p = idx >> 4, ch = idx & 15;
        int trow = p / 34, tcol = p - trow*34;
        int ih = h0 - 1 + trow, iw = tcol - 1;
        u32 dst = sb + p*272 + ch*16;
        if ((unsigned)ih < 32u && (unsigned)iw < 32u){
            const char* src = (const char*)(ps.in + ((size_t)((b*Hc + ih)*Wc + iw) << 7)) + ch*16;
            CP16(dst, src);
        } else {
            asm volatile("st.shared.v4.b32 [%0], {%1,%1,%1,%1};"::"r"(dst),"r"(0):"memory");
        }
    }
    // ---- stage weights for tap 0 into buf 0 ----
    {
        for (int idx = tid; idx < Et*1024; idx += 256){
            int e = idx >> 10, rem = idx & 1023, row = rem >> 4, ch = rem & 15;
            u32 dst = sbW + (e*64 + row)*272 + ch*16;
            const char* src = (const char*)d_wm + (((size_t)(ps.l[e]*9 + 0)*64 + row) << 8) + ch*16;
            CP16(dst, src);
        }
    }
    CPCOMMIT();

    // ldmatrix lane patterns
    const int g = lane >> 3, lm = lane & 7;
    const u32 patB = (u32)(((g&2)?8:0) + lm)*272 + ((g&1)?16:0);
    const u32 patA = (u32)(((g&1)?8:0) + lm)*272 + ((g&2)?16:0);
    int Arow[2*Et];
    #pragma unroll
    for (int j = 0; j < 2*Et; j++){
        int t = wm*2*Et + j;
        Arow[j] = ((t>>2)*64 + (t&3)*16)*272;
    }

    float acc[2*Et][4][4];
    #pragma unroll
    for (int j = 0; j < 2*Et; j++)
        #pragma unroll
        for (int nt = 0; nt < 4; nt++)
            #pragma unroll
            for (int q = 0; q < 4; q++) acc[j][nt][q] = 0.f;

    #pragma unroll 1
    for (int tap = 0; tap < 9; tap++){
        if (tap + 1 < 9){
            int buf = (tap + 1) & 1;
            for (int idx = tid; idx < Et*1024; idx += 256){
                int e = idx >> 10, rem = idx & 1023, row = rem >> 4, ch = rem & 15;
                u32 dst = sbW + buf*WBUF + (e*64 + row)*272 + ch*16;
                const char* src = (const char*)d_wm + (((size_t)(ps.l[e]*9 + tap + 1)*64 + row) << 8) + ch*16;
                CP16(dst, src);
            }
            CPCOMMIT();
            CPWAIT1();
        } else {
            CPCOMMIT();
            CPWAIT0();
        }
        __syncthreads();

        const int ky = tap / 3, kx = tap - ky*3;
        const u32 pB = sb + (u32)((wn + ky)*34 + kx)*272 + patB;
        const u32 pA = sbW + (tap & 1)*WBUF + patA;

        #pragma unroll
        for (int chunk = 0; chunk < 3; chunk++){
            const int wk2 = (chunk==1) ? 128 : 0;   // weight k byte offset (lo chunk)
            const int ik2 = (chunk==2) ? 128 : 0;   // input k byte offset (lo chunk)
            #pragma unroll
            for (int kk = 0; kk < 4; kk++){
                u32 b0,b1,b2,b3,b4,b5,b6,b7;
                LDSM4(b0,b1,b2,b3, pB + ik2 + 32*kk);
                LDSM4(b4,b5,b6,b7, pB + ik2 + 32*kk + 16*272);
                #pragma unroll
                for (int j = 0; j < 2*Et; j++){
                    u32 a0,a1,a2,a3;
                    LDSM4(a0,a1,a2,a3, pA + Arow[j] + wk2 + 32*kk);
                    MMA(acc[j][0], a0,a1,a2,a3, b0,b1);
                    MMA(acc[j][1], a0,a1,a2,a3, b2,b3);
                    MMA(acc[j][2], a0,a1,a2,a3, b4,b5);
                    MMA(acc[j][3], a0,a1,a2,a3, b6,b7);
                }
            }
        }
        __syncthreads();
    }

    // ---------------- epilogue ----------------
    const int h = h0 + wn;
    #pragma unroll
    for (int j = 0; j < 2*Et; j++){
        int t = wm*2*Et + j;
        int e = t >> 2;
        int ocb = (t & 3)*16 + (lane >> 2);
        int mode = ps.mode[e];
        const float* add = ps.addin[e];
        #pragma unroll
        for (int nt = 0; nt < 4; nt++){
            int wcol = nt*8 + 2*(lane & 3);
            #pragma unroll
            for (int half = 0; half < 2; half++){
                int oc = ocb + half*8;
                float v0 = acc[j][nt][half*2 + 0];
                float v1 = acc[j][nt][half*2 + 1];
                size_t base = (((size_t)b*Cc + oc)*Hc + h)*Wc + wcol;
                if (add){
                    float2 a2 = *(const float2*)(add + base);
                    v0 += a2.x; v1 += a2.y;
                }
                if (mode == 0){
                    *(float2*)((float*)ps.outA[e] + base) = make_float2(v0, v1);
                } else if (mode == 1){
                    float ai = d_ain[oc], ao = d_aout[oc];
                    v0 = ai * fmaxf(ao * v0, 0.f);
                    v1 = ai * fmaxf(ao * v1, 0.f);
                    __nv_bfloat16 h0b = __float2bfloat16(v0);
                    __nv_bfloat16 h1b = __float2bfloat16(v1);
                    __nv_bfloat16 l0b = __float2bfloat16(v0 - __bfloat162float(h0b));
                    __nv_bfloat16 l1b = __float2bfloat16(v1 - __bfloat162float(h1b));
                    __nv_bfloat16* ox = (__nv_bfloat16*)ps.outA[e];
                    size_t pos = ((size_t)b*Hc + h)*Wc + wcol;
                    ox[pos*128 + oc]            = h0b;
                    ox[pos*128 + 64 + oc]       = l0b;
                    ox[(pos+1)*128 + oc]        = h1b;
                    ox[(pos+1)*128 + 64 + oc]   = l1b;
                } else {
                    float ao = d_aout[oc];
                    *(float2*)((float*)ps.outA[e] + base) = make_float2(ao*v0, ao*v1);
                }
            }
        }
    }
}

// ---------------- launch ----------------
extern "C" void kernel_launch(void* const* d_in, const int* in_sizes, int n_in,
                              void* d_out, int out_size){
    const float *x=nullptr, *a1=nullptr, *a2=nullptr, *W=nullptr;
    for (int i=0;i<n_in;i++){
        if (in_sizes[i]==TOTSZ) x=(const float*)d_in[i];
        else if (in_sizes[i]==WSZ) W=(const float*)d_in[i];
        else if (in_sizes[i]==8){ if(!a1) a1=(const float*)d_in[i]; else a2=(const float*)d_in[i]; }
    }
    float* out = (float*)d_out;

    __nv_bfloat16 *x0p,*x1p,*x2p;
    float *acc2,*acc3;
    cudaGetSymbolAddress((void**)&x0p,d_x0);
    cudaGetSymbolAddress((void**)&x1p,d_x1);
    cudaGetSymbolAddress((void**)&x2p,d_x2);
    cudaGetSymbolAddress((void**)&acc2,d_acc2);
    cudaGetSymbolAddress((void**)&acc3,d_acc3);

    const int smem3 = SM_IN_SZ + 2*3*64*272;   // 159936
    const int smem2 = SM_IN_SZ + 2*2*64*272;   // 125120
    const int smem1 = SM_IN_SZ + 2*1*64*272;   // 90304
    cudaFuncSetAttribute(conv_mma_kernel<3>, cudaFuncAttributeMaxDynamicSharedMemorySize, smem3);
    cudaFuncSetAttribute(conv_mma_kernel<2>, cudaFuncAttributeMaxDynamicSharedMemorySize, smem2);
    cudaFuncSetAttribute(conv_mma_kernel<1>, cudaFuncAttributeMaxDynamicSharedMemorySize, smem1);

    scales_kernel<<<1, 64>>>(a1, a2);
    wprep_kernel<<<(NEDGE*9*Cc*Cc + 255)/256, 256>>>(W);
    inprep_kernel<<<dim3(Hc, Bc), 256>>>(x);

    // Pass A: x0 -> { W0 -> x1 (mode1), W1 -> acc2 (mode0), W3 -> acc3 (mode0) }
    PassSpec pa{};
    pa.l[0]=0; pa.mode[0]=1; pa.addin[0]=nullptr; pa.outA[0]=x1p;
    pa.l[1]=1; pa.mode[1]=0; pa.addin[1]=nullptr; pa.outA[1]=acc2;
    pa.l[2]=3; pa.mode[2]=0; pa.addin[2]=nullptr; pa.outA[2]=acc3;
    pa.in = x0p;
    conv_mma_kernel<3><<<dim3(8, Bc), 256, smem3>>>(pa);

    // Pass B: x1 -> { W2 + acc2 -> x2 (mode1), W4 + acc3 -> acc3 (mode0) }
    PassSpec pb{};
    pb.l[0]=2; pb.mode[0]=1; pb.addin[0]=acc2; pb.outA[0]=x2p;
    pb.l[1]=4; pb.mode[1]=0; pb.addin[1]=acc3; pb.outA[1]=acc3;
    pb.in = x1p;
    conv_mma_kernel<2><<<dim3(8, Bc), 256, smem2>>>(pb);

    // Pass C: x2 -> { W5 + acc3 -> out (mode2) }
    PassSpec pc{};
    pc.l[0]=5; pc.mode[0]=2; pc.addin[0]=acc3; pc.outA[0]=out;
    pc.in = x2p;
    conv_mma_kernel<1><<<dim3(8, Bc), 256, smem1>>>(pc);

    (void)out_size;
}

// round 7
// speedup vs baseline: 2.2676x; 1.0323x over previous
#include <cuda_runtime.h>
#include <cuda_bf16.h>
#include <cstdint>

#define Bc 128
#define Cc 64
#define Hc 32
#define Wc 32
#define NEDGE 6
#define TOTSZ (Bc*Cc*Hc*Wc)
#define WSZ   (NEDGE*Cc*Cc*9)

typedef unsigned int u32;

// ---------------- device scratch ----------------
// activations: [b][h][w][128] bf16, k=0..63 hi(ci), k=64..127 lo(ci)
__device__ __align__(16) __nv_bfloat16 d_x0[TOTSZ*2];
__device__ __align__(16) __nv_bfloat16 d_x1[TOTSZ*2];
__device__ __align__(16) __nv_bfloat16 d_x2[TOTSZ*2];
__device__ float d_acc2[TOTSZ];     // NCHW fp32
__device__ float d_acc3[TOTSZ];     // NCHW fp32
// weights: [l][s][oc][128] bf16, k=0..63 hi(ci), 64..127 lo(ci)
__device__ __align__(16) __nv_bfloat16 d_wm[NEDGE*9*Cc*128];
__device__ float d_ain[Cc], d_aout[Cc];

// ---------------- PTX helpers (baseline sm_80+ PTX only) ----------------
__device__ __forceinline__ u32 smem_u32(const void* p){
    u32 a; asm("{ .reg .u64 t; cvta.to.shared.u64 t, %1; cvt.u32.u64 %0, t; }":"=r"(a):"l"(p)); return a;
}
#define CP16(dst,src) asm volatile("cp.async.ca.shared.global [%0], [%1], 16;"::"r"(dst),"l"(src):"memory")
#define CPCOMMIT()    asm volatile("cp.async.commit_group;":::"memory")
#define CPWAIT1()     asm volatile("cp.async.wait_group 1;":::"memory")
#define CPWAIT0()     asm volatile("cp.async.wait_group 0;":::"memory")

#define LDSM4(r0,r1,r2,r3,addr) \
    asm volatile("ldmatrix.sync.aligned.m8n8.x4.shared.b16 {%0,%1,%2,%3}, [%4];" \
        : "=r"(r0),"=r"(r1),"=r"(r2),"=r"(r3) : "r"(addr))

#define MMA(c,a0,a1,a2,a3,b0,b1) \
    asm volatile("mma.sync.aligned.m16n8k16.row.col.f32.bf16.bf16.f32 " \
        "{%0,%1,%2,%3},{%4,%5,%6,%7},{%8,%9},{%0,%1,%2,%3};" \
        : "+f"((c)[0]),"+f"((c)[1]),"+f"((c)[2]),"+f"((c)[3]) \
        : "r"(a0),"r"(a1),"r"(a2),"r"(a3),"r"(b0),"r"(b1))

// ---------------- prep kernels ----------------
__global__ void scales_kernel(const float* __restrict__ a1, const float* __restrict__ a2){
    int c = threadIdx.x;
    if (c < Cc){
        float s1=0.f, s2=0.f;
        #pragma unroll
        for (int i=0;i<8;i++) if (c < 8*(i+1)) { s1+=a1[i]; s2+=a2[i]; }
        d_ain[c]=s1; d_aout[c]=s2;
    }
}

// W OIHW -> [l][s][oc][128] bf16 (hi|lo)
__global__ void wprep_kernel(const float* __restrict__ W){
    int idx = blockIdx.x*256 + threadIdx.x;
    if (idx >= NEDGE*9*Cc*Cc) return;
    int ci = idx & 63, t = idx >> 6;
    int oc = t & 63; t >>= 6;
    int s = t % 9, l = t / 9;
    float w = W[(((l*Cc + oc)*Cc + ci)*9) + s];
    __nv_bfloat16 hb = __float2bfloat16(w);
    __nv_bfloat16 lb = __float2bfloat16(w - __bfloat162float(hb));
    size_t base = (size_t)((l*9 + s)*Cc + oc) * 128;
    d_wm[base + ci]      = hb;
    d_wm[base + 64 + ci] = lb;
}

// x NCHW fp32 -> d_x0 [b][h][w][128] with a_in*relu and hi/lo split
__global__ void inprep_kernel(const float* __restrict__ x){
    __shared__ float tile[Cc][Wc+1];
    int b = blockIdx.y, h = blockIdx.x, t = threadIdx.x;
    int w = t & 31, cb = t >> 5;
    #pragma unroll
    for (int i=0;i<8;i++){
        int c = cb*8 + i;
        tile[c][w] = x[(((size_t)b*Cc + c)*Hc + h)*Wc + w];
    }
    __syncthreads();
    int w2 = t >> 3, cg = (t & 7) * 8;
    u32 hi[4], lo[4];
    #pragma unroll
    for (int i=0;i<4;i++){
        int c = cg + i*2;
        float v0 = d_ain[c]   * fmaxf(tile[c][w2],   0.f);
        float v1 = d_ain[c+1] * fmaxf(tile[c+1][w2], 0.f);
        __nv_bfloat16 h0b=__float2bfloat16(v0), h1b=__float2bfloat16(v1);
        __nv_bfloat16 l0b=__float2bfloat16(v0-__bfloat162float(h0b));
        __nv_bfloat16 l1b=__float2bfloat16(v1-__bfloat162float(h1b));
        hi[i]=(u32)__bfloat16_as_ushort(h0b)|((u32)__bfloat16_as_ushort(h1b)<<16);
        lo[i]=(u32)__bfloat16_as_ushort(l0b)|((u32)__bfloat16_as_ushort(l1b)<<16);
    }
    size_t pos = ((size_t)b*Hc + h)*Wc + w2;
    *(uint4*)(d_x0 + pos*128 + cg)      = make_uint4(hi[0],hi[1],hi[2],hi[3]);
    *(uint4*)(d_x0 + pos*128 + 64 + cg) = make_uint4(lo[0],lo[1],lo[2],lo[3]);
}

// ---------------- conv pass (mma.sync bf16, 512 threads) ----------------
struct PassSpec {
    int l[3];
    int mode[3];            // 0: fp32 NCHW acc; 1: relu+split -> next d_x; 2: final NCHW out
    const float* addin[3];  // NCHW fp32 or null
    void* outA[3];
    const __nv_bfloat16* in;
};

// smem: input tile [204 pos][272B], then 2 weight bufs [E*64 oc][272B]
#define SM_IN_SZ (204*272)
#define NT 512

template<int Et>
__global__ __launch_bounds__(NT, 1)
void conv_mma_kernel(PassSpec ps){
    extern __shared__ __align__(16) char smem[];
    const u32 sb  = smem_u32(smem);
    const int tid = threadIdx.x;
    const int lane = tid & 31, wrp = tid >> 5;
    const int wn = wrp & 3, wm = wrp >> 2;        // 4 n-rows x 4 m-groups
    const int band = blockIdx.x, b = blockIdx.y;
    const int h0 = band * 4;
    const int WBUF = Et*64*272;
    const u32 sbW = sb + SM_IN_SZ;

    // ---- stage input tile: 204 pos rows x 256B (+16B pad) ----
    for (int idx = tid; idx < 204*16; idx += NT){
        int p = idx >> 4, ch = idx & 15;
        int trow = p / 34, tcol = p - trow*34;
        int ih = h0 - 1 + trow, iw = tcol - 1;
        u32 dst = sb + p*272 + ch*16;
        if ((unsigned)ih < 32u && (unsigned)iw < 32u){
            const char* src = (const char*)(ps.in + ((size_t)((b*Hc + ih)*Wc + iw) << 7)) + ch*16;
            CP16(dst, src);
        } else {
            asm volatile("st.shared.v4.b32 [%0], {%1,%1,%1,%1};"::"r"(dst),"r"(0):"memory");
        }
    }
    // ---- stage weights for tap 0 into buf 0 ----
    for (int idx = tid; idx < Et*1024; idx += NT){
        int e = idx >> 10, rem = idx & 1023, row = rem >> 4, ch = rem & 15;
        u32 dst = sbW + (e*64 + row)*272 + ch*16;
        const char* src = (const char*)d_wm + (((size_t)(ps.l[e]*9 + 0)*64 + row) << 8) + ch*16;
        CP16(dst, src);
    }
    CPCOMMIT();

    // ldmatrix lane patterns
    const int g = lane >> 3, lm = lane & 7;
    const u32 patB = (u32)(((g&2)?8:0) + lm)*272 + ((g&1)?16:0);
    const u32 patA = (u32)(((g&1)?8:0) + lm)*272 + ((g&2)?16:0);
    int Arow[Et];
    #pragma unroll
    for (int j = 0; j < Et; j++){
        int t = wm*Et + j;
        Arow[j] = ((t>>2)*64 + (t&3)*16)*272;
    }

    float acc[Et][4][4];
    #pragma unroll
    for (int j = 0; j < Et; j++)
        #pragma unroll
        for (int nt = 0; nt < 4; nt++)
            #pragma unroll
            for (int q = 0; q < 4; q++) acc[j][nt][q] = 0.f;

    #pragma unroll 1
    for (int tap = 0; tap < 9; tap++){
        if (tap + 1 < 9){
            int buf = (tap + 1) & 1;
            for (int idx = tid; idx < Et*1024; idx += NT){
                int e = idx >> 10, rem = idx & 1023, row = rem >> 4, ch = rem & 15;
                u32 dst = sbW + buf*WBUF + (e*64 + row)*272 + ch*16;
                const char* src = (const char*)d_wm + (((size_t)(ps.l[e]*9 + tap + 1)*64 + row) << 8) + ch*16;
                CP16(dst, src);
            }
            CPCOMMIT();
            CPWAIT1();
        } else {
            CPCOMMIT();
            CPWAIT0();
        }
        __syncthreads();

        const int ky = tap / 3, kx = tap - ky*3;
        const u32 pB = sb + (u32)((wn + ky)*34 + kx)*272 + patB;
        const u32 pA = sbW + (tap & 1)*WBUF + patA;

        #pragma unroll
        for (int chunk = 0; chunk < 3; chunk++){
            const int wk2 = (chunk==1) ? 128 : 0;   // weight k byte offset (lo chunk)
            const int ik2 = (chunk==2) ? 128 : 0;   // input k byte offset (lo chunk)
            #pragma unroll
            for (int kk = 0; kk < 4; kk++){
                u32 b0,b1,b2,b3,b4,b5,b6,b7;
                LDSM4(b0,b1,b2,b3, pB + ik2 + 32*kk);
                LDSM4(b4,b5,b6,b7, pB + ik2 + 32*kk + 16*272);
                #pragma unroll
                for (int j = 0; j < Et; j++){
                    u32 a0,a1,a2,a3;
                    LDSM4(a0,a1,a2,a3, pA + Arow[j] + wk2 + 32*kk);
                    MMA(acc[j][0], a0,a1,a2,a3, b0,b1);
                    MMA(acc[j][1], a0,a1,a2,a3, b2,b3);
                    MMA(acc[j][2], a0,a1,a2,a3, b4,b5);
                    MMA(acc[j][3], a0,a1,a2,a3, b6,b7);
                }
            }
        }
        __syncthreads();
    }

    // ---------------- epilogue ----------------
    const int h = h0 + wn;
    #pragma unroll
    for (int j = 0; j < Et; j++){
        int t = wm*Et + j;
        int e = t >> 2;
        int ocb = (t & 3)*16 + (lane >> 2);
        int mode = ps.mode[e];
        const float* add = ps.addin[e];
        #pragma unroll
        for (int nt = 0; nt < 4; nt++){
            int wcol = nt*8 + 2*(lane & 3);
            #pragma unroll
            for (int half = 0; half < 2; half++){
                int oc = ocb + half*8;
                float v0 = acc[j][nt][half*2 + 0];
                float v1 = acc[j][nt][half*2 + 1];
                size_t base = (((size_t)b*Cc + oc)*Hc + h)*Wc + wcol;
                if (add){
                    float2 a2 = *(const float2*)(add + base);
                    v0 += a2.x; v1 += a2.y;
                }
                if (mode == 0){
                    *(float2*)((float*)ps.outA[e] + base) = make_float2(v0, v1);
                } else if (mode == 1){
                    float ai = d_ain[oc], ao = d_aout[oc];
                    v0 = ai * fmaxf(ao * v0, 0.f);
                    v1 = ai * fmaxf(ao * v1, 0.f);
                    __nv_bfloat16 h0b = __float2bfloat16(v0);
                    __nv_bfloat16 h1b = __float2bfloat16(v1);
                    __nv_bfloat16 l0b = __float2bfloat16(v0 - __bfloat162float(h0b));
                    __nv_bfloat16 l1b = __float2bfloat16(v1 - __bfloat162float(h1b));
                    __nv_bfloat16* ox = (__nv_bfloat16*)ps.outA[e];
                    size_t pos = ((size_t)b*Hc + h)*Wc + wcol;
                    ox[pos*128 + oc]            = h0b;
                    ox[pos*128 + 64 + oc]       = l0b;
                    ox[(pos+1)*128 + oc]        = h1b;
                    ox[(pos+1)*128 + 64 + oc]   = l1b;
                } else {
                    float ao = d_aout[oc];
                    *(float2*)((float*)ps.outA[e] + base) = make_float2(ao*v0, ao*v1);
                }
            }
        }
    }
}

// ---------------- launch ----------------
extern "C" void kernel_launch(void* const* d_in, const int* in_sizes, int n_in,
                              void* d_out, int out_size){
    const float *x=nullptr, *a1=nullptr, *a2=nullptr, *W=nullptr;
    for (int i=0;i<n_in;i++){
        if (in_sizes[i]==TOTSZ) x=(const float*)d_in[i];
        else if (in_sizes[i]==WSZ) W=(const float*)d_in[i];
        else if (in_sizes[i]==8){ if(!a1) a1=(const float*)d_in[i]; else a2=(const float*)d_in[i]; }
    }
    float* out = (float*)d_out;

    __nv_bfloat16 *x0p,*x1p,*x2p;
    float *acc2,*acc3;
    cudaGetSymbolAddress((void**)&x0p,d_x0);
    cudaGetSymbolAddress((void**)&x1p,d_x1);
    cudaGetSymbolAddress((void**)&x2p,d_x2);
    cudaGetSymbolAddress((void**)&acc2,d_acc2);
    cudaGetSymbolAddress((void**)&acc3,d_acc3);

    const int smem3 = SM_IN_SZ + 2*3*64*272;
    const int smem2 = SM_IN_SZ + 2*2*64*272;
    const int smem1 = SM_IN_SZ + 2*1*64*272;
    cudaFuncSetAttribute(conv_mma_kernel<3>, cudaFuncAttributeMaxDynamicSharedMemorySize, smem3);
    cudaFuncSetAttribute(conv_mma_kernel<2>, cudaFuncAttributeMaxDynamicSharedMemorySize, smem2);
    cudaFuncSetAttribute(conv_mma_kernel<1>, cudaFuncAttributeMaxDynamicSharedMemorySize, smem1);

    scales_kernel<<<1, 64>>>(a1, a2);
    wprep_kernel<<<(NEDGE*9*Cc*Cc + 255)/256, 256>>>(W);
    inprep_kernel<<<dim3(Hc, Bc), 256>>>(x);

    // Pass A: x0 -> { W0 -> x1 (mode1), W1 -> acc2 (mode0), W3 -> acc3 (mode0) }
    PassSpec pa{};
    pa.l[0]=0; pa.mode[0]=1; pa.addin[0]=nullptr; pa.outA[0]=x1p;
    pa.l[1]=1; pa.mode[1]=0; pa.addin[1]=nullptr; pa.outA[1]=acc2;
    pa.l[2]=3; pa.mode[2]=0; pa.addin[2]=nullptr; pa.outA[2]=acc3;
    pa.in = x0p;
    conv_mma_kernel<3><<<dim3(8, Bc), NT, smem3>>>(pa);

    // Pass B: x1 -> { W2 + acc2 -> x2 (mode1), W4 + acc3 -> acc3 (mode0) }
    PassSpec pb{};
    pb.l[0]=2; pb.mode[0]=1; pb.addin[0]=acc2; pb.outA[0]=x2p;
    pb.l[1]=4; pb.mode[1]=0; pb.addin[1]=acc3; pb.outA[1]=acc3;
    pb.in = x1p;
    conv_mma_kernel<2><<<dim3(8, Bc), NT, smem2>>>(pb);

    // Pass C: x2 -> { W5 + acc3 -> out (mode2) }
    PassSpec pc{};
    pc.l[0]=5; pc.mode[0]=2; pc.addin[0]=acc3; pc.outA[0]=out;
    pc.in = x2p;
    conv_mma_kernel<1><<<dim3(8, Bc), NT, smem1>>>(pc);

    (void)out_size;
}

// round 8
// speedup vs baseline: 2.5440x; 1.1219x over previous
#include <cuda_runtime.h>
#include <cuda_bf16.h>
#include <cstdint>

#define Bc 128
#define Cc 64
#define Hc 32
#define Wc 32
#define NEDGE 6
#define TOTSZ (Bc*Cc*Hc*Wc)
#define WSZ   (NEDGE*Cc*Cc*9)

typedef unsigned int u32;

// ---------------- device scratch ----------------
// activations: [b][h][w][128] bf16, k=0..63 hi(ci), k=64..127 lo(ci)
__device__ __align__(16) __nv_bfloat16 d_x0[TOTSZ*2];
__device__ __align__(16) __nv_bfloat16 d_x1[TOTSZ*2];
__device__ __align__(16) __nv_bfloat16 d_x2[TOTSZ*2];
__device__ float d_acc2[TOTSZ];     // NCHW fp32
__device__ float d_acc3[TOTSZ];     // NCHW fp32
// weights: [l][s][oc][128] bf16, k=0..63 hi(ci), 64..127 lo(ci)
__device__ __align__(16) __nv_bfloat16 d_wm[NEDGE*9*Cc*128];
__device__ float d_ain[Cc], d_aout[Cc];

// ---------------- PTX helpers (baseline sm_80+ PTX only) ----------------
__device__ __forceinline__ u32 smem_u32(const void* p){
    u32 a; asm("{ .reg .u64 t; cvta.to.shared.u64 t, %1; cvt.u32.u64 %0, t; }":"=r"(a):"l"(p)); return a;
}
#define CP16(dst,src) asm volatile("cp.async.ca.shared.global [%0], [%1], 16;"::"r"(dst),"l"(src):"memory")
#define CPCOMMIT()    asm volatile("cp.async.commit_group;":::"memory")
#define CPWAIT1()     asm volatile("cp.async.wait_group 1;":::"memory")
#define CPWAIT0()     asm volatile("cp.async.wait_group 0;":::"memory")

#define LDSM4(r0,r1,r2,r3,addr) \
    asm volatile("ldmatrix.sync.aligned.m8n8.x4.shared.b16 {%0,%1,%2,%3}, [%4];" \
        : "=r"(r0),"=r"(r1),"=r"(r2),"=r"(r3) : "r"(addr))

#define MMA(c,a0,a1,a2,a3,b0,b1) \
    asm volatile("mma.sync.aligned.m16n8k16.row.col.f32.bf16.bf16.f32 " \
        "{%0,%1,%2,%3},{%4,%5,%6,%7},{%8,%9},{%0,%1,%2,%3};" \
        : "+f"((c)[0]),"+f"((c)[1]),"+f"((c)[2]),"+f"((c)[3]) \
        : "r"(a0),"r"(a1),"r"(a2),"r"(a3),"r"(b0),"r"(b1))

// ---------------- prep kernels ----------------
__global__ void scales_kernel(const float* __restrict__ a1, const float* __restrict__ a2){
    int c = threadIdx.x;
    if (c < Cc){
        float s1=0.f, s2=0.f;
        #pragma unroll
        for (int i=0;i<8;i++) if (c < 8*(i+1)) { s1+=a1[i]; s2+=a2[i]; }
        d_ain[c]=s1; d_aout[c]=s2;
    }
}

// W OIHW -> [l][s][oc][128] bf16 (hi|lo)
__global__ void wprep_kernel(const float* __restrict__ W){
    int idx = blockIdx.x*256 + threadIdx.x;
    if (idx >= NEDGE*9*Cc*Cc) return;
    int ci = idx & 63, t = idx >> 6;
    int oc = t & 63; t >>= 6;
    int s = t % 9, l = t / 9;
    float w = W[(((l*Cc + oc)*Cc + ci)*9) + s];
    __nv_bfloat16 hb = __float2bfloat16(w);
    __nv_bfloat16 lb = __float2bfloat16(w - __bfloat162float(hb));
    size_t base = (size_t)((l*9 + s)*Cc + oc) * 128;
    d_wm[base + ci]      = hb;
    d_wm[base + 64 + ci] = lb;
}

// x NCHW fp32 -> d_x0 [b][h][w][128] with a_in*relu and hi/lo split
__global__ void inprep_kernel(const float* __restrict__ x){
    __shared__ float tile[Cc][Wc+1];
    int b = blockIdx.y, h = blockIdx.x, t = threadIdx.x;
    int w = t & 31, cb = t >> 5;
    #pragma unroll
    for (int i=0;i<8;i++){
        int c = cb*8 + i;
        tile[c][w] = x[(((size_t)b*Cc + c)*Hc + h)*Wc + w];
    }
    __syncthreads();
    int w2 = t >> 3, cg = (t & 7) * 8;
    u32 hi[4], lo[4];
    #pragma unroll
    for (int i=0;i<4;i++){
        int c = cg + i*2;
        float v0 = d_ain[c]   * fmaxf(tile[c][w2],   0.f);
        float v1 = d_ain[c+1] * fmaxf(tile[c+1][w2], 0.f);
        __nv_bfloat16 h0b=__float2bfloat16(v0), h1b=__float2bfloat16(v1);
        __nv_bfloat16 l0b=__float2bfloat16(v0-__bfloat162float(h0b));
        __nv_bfloat16 l1b=__float2bfloat16(v1-__bfloat162float(h1b));
        hi[i]=(u32)__bfloat16_as_ushort(h0b)|((u32)__bfloat16_as_ushort(h1b)<<16);
        lo[i]=(u32)__bfloat16_as_ushort(l0b)|((u32)__bfloat16_as_ushort(l1b)<<16);
    }
    size_t pos = ((size_t)b*Hc + h)*Wc + w2;
    *(uint4*)(d_x0 + pos*128 + cg)      = make_uint4(hi[0],hi[1],hi[2],hi[3]);
    *(uint4*)(d_x0 + pos*128 + 64 + cg) = make_uint4(lo[0],lo[1],lo[2],lo[3]);
}

// ---------------- conv pass (mma.sync bf16, 512 threads) ----------------
struct PassSpec {
    int l[3];
    int mode[3];            // 0: fp32 NCHW acc; 1: relu+split -> next d_x; 2: final NCHW out
    const float* addin[3];  // NCHW fp32 or null
    void* outA[3];
    const __nv_bfloat16* in;
};

// smem: input tile [204 pos][272B], then 2 weight bufs [E*64 oc][272B]
#define SM_IN_SZ (204*272)
#define NT 512

template<int Et>
__global__ __launch_bounds__(NT, 1)
void conv_mma_kernel(PassSpec ps){
    extern __shared__ __align__(16) char smem[];
    const u32 sb  = smem_u32(smem);
    const int tid = threadIdx.x;
    const int lane = tid & 31, wrp = tid >> 5;
    const int wn = wrp & 3, wm = wrp >> 2;        // 4 n-rows x 4 m-groups
    const int band = blockIdx.x, b = blockIdx.y;
    const int h0 = band * 4;
    const int WBUF = Et*64*272;
    const u32 sbW = sb + SM_IN_SZ;

    // ---- stage input tile: 204 pos rows x 256B (+16B pad) ----
    for (int idx = tid; idx < 204*16; idx += NT){
        int p = idx >> 4, ch = idx & 15;
        int trow = p / 34, tcol = p - trow*34;
        int ih = h0 - 1 + trow, iw = tcol - 1;
        u32 dst = sb + p*272 + ch*16;
        if ((unsigned)ih < 32u && (unsigned)iw < 32u){
            const char* src = (const char*)(ps.in + ((size_t)((b*Hc + ih)*Wc + iw) << 7)) + ch*16;
            CP16(dst, src);
        } else {
            asm volatile("st.shared.v4.b32 [%0], {%1,%1,%1,%1};"::"r"(dst),"r"(0):"memory");
        }
    }
    // ---- stage weights for tap 0 into buf 0 ----
    for (int idx = tid; idx < Et*1024; idx += NT){
        int e = idx >> 10, rem = idx & 1023, row = rem >> 4, ch = rem & 15;
        u32 dst = sbW + (e*64 + row)*272 + ch*16;
        const char* src = (const char*)d_wm + (((size_t)(ps.l[e]*9 + 0)*64 + row) << 8) + ch*16;
        CP16(dst, src);
    }
    CPCOMMIT();

    // ldmatrix lane patterns
    const int g = lane >> 3, lm = lane & 7;
    const u32 patB = (u32)(((g&2)?8:0) + lm)*272 + ((g&1)?16:0);
    const u32 patA = (u32)(((g&1)?8:0) + lm)*272 + ((g&2)?16:0);
    int Arow[Et];
    #pragma unroll
    for (int j = 0; j < Et; j++){
        int t = wm*Et + j;
        Arow[j] = ((t>>2)*64 + (t&3)*16)*272;
    }

    float acc[Et][4][4];
    #pragma unroll
    for (int j = 0; j < Et; j++)
        #pragma unroll
        for (int nt = 0; nt < 4; nt++)
            #pragma unroll
            for (int q = 0; q < 4; q++) acc[j][nt][q] = 0.f;

    #pragma unroll 1
    for (int tap = 0; tap < 9; tap++){
        if (tap + 1 < 9){
            int buf = (tap + 1) & 1;
            for (int idx = tid; idx < Et*1024; idx += NT){
                int e = idx >> 10, rem = idx & 1023, row = rem >> 4, ch = rem & 15;
                u32 dst = sbW + buf*WBUF + (e*64 + row)*272 + ch*16;
                const char* src = (const char*)d_wm + (((size_t)(ps.l[e]*9 + tap + 1)*64 + row) << 8) + ch*16;
                CP16(dst, src);
            }
            CPCOMMIT();
            CPWAIT1();
        } else {
            CPCOMMIT();
            CPWAIT0();
        }
        __syncthreads();

        const int ky = tap / 3, kx = tap - ky*3;
        const u32 pB = sb + (u32)((wn + ky)*34 + kx)*272 + patB;
        const u32 pA = sbW + (tap & 1)*WBUF + patA;

        // fragment-reuse inner loop: chunks share A_hi (products 0,2) and B_hi (products 0,1)
        #pragma unroll
        for (int kk = 0; kk < 4; kk++){
            u32 bh0,bh1,bh2,bh3,bh4,bh5,bh6,bh7;
            u32 bl0,bl1,bl2,bl3,bl4,bl5,bl6,bl7;
            LDSM4(bh0,bh1,bh2,bh3, pB + 32*kk);
            LDSM4(bh4,bh5,bh6,bh7, pB + 32*kk + 16*272);
            LDSM4(bl0,bl1,bl2,bl3, pB + 128 + 32*kk);
            LDSM4(bl4,bl5,bl6,bl7, pB + 128 + 32*kk + 16*272);
            #pragma unroll
            for (int j = 0; j < Et; j++){
                u32 ah0,ah1,ah2,ah3, al0,al1,al2,al3;
                LDSM4(ah0,ah1,ah2,ah3, pA + Arow[j] + 32*kk);
                LDSM4(al0,al1,al2,al3, pA + Arow[j] + 128 + 32*kk);
                // A_hi x B_hi
                MMA(acc[j][0], ah0,ah1,ah2,ah3, bh0,bh1);
                MMA(acc[j][1], ah0,ah1,ah2,ah3, bh2,bh3);
                MMA(acc[j][2], ah0,ah1,ah2,ah3, bh4,bh5);
                MMA(acc[j][3], ah0,ah1,ah2,ah3, bh6,bh7);
                // A_lo x B_hi
                MMA(acc[j][0], al0,al1,al2,al3, bh0,bh1);
                MMA(acc[j][1], al0,al1,al2,al3, bh2,bh3);
                MMA(acc[j][2], al0,al1,al2,al3, bh4,bh5);
                MMA(acc[j][3], al0,al1,al2,al3, bh6,bh7);
                // A_hi x B_lo
                MMA(acc[j][0], ah0,ah1,ah2,ah3, bl0,bl1);
                MMA(acc[j][1], ah0,ah1,ah2,ah3, bl2,bl3);
                MMA(acc[j][2], ah0,ah1,ah2,ah3, bl4,bl5);
                MMA(acc[j][3], ah0,ah1,ah2,ah3, bl6,bl7);
            }
        }
        __syncthreads();
    }

    // ---------------- epilogue ----------------
    const int h = h0 + wn;
    #pragma unroll
    for (int j = 0; j < Et; j++){
        int t = wm*Et + j;
        int e = t >> 2;
        int ocb = (t & 3)*16 + (lane >> 2);
        int mode = ps.mode[e];
        const float* add = ps.addin[e];
        #pragma unroll
        for (int nt = 0; nt < 4; nt++){
            int wcol = nt*8 + 2*(lane & 3);
            #pragma unroll
            for (int half = 0; half < 2; half++){
                int oc = ocb + half*8;
                float v0 = acc[j][nt][half*2 + 0];
                float v1 = acc[j][nt][half*2 + 1];
                size_t base = (((size_t)b*Cc + oc)*Hc + h)*Wc + wcol;
                if (add){
                    float2 a2 = *(const float2*)(add + base);
                    v0 += a2.x; v1 += a2.y;
                }
                if (mode == 0){
                    *(float2*)((float*)ps.outA[e] + base) = make_float2(v0, v1);
                } else if (mode == 1){
                    float ai = d_ain[oc], ao = d_aout[oc];
                    v0 = ai * fmaxf(ao * v0, 0.f);
                    v1 = ai * fmaxf(ao * v1, 0.f);
                    __nv_bfloat16 h0b = __float2bfloat16(v0);
                    __nv_bfloat16 h1b = __float2bfloat16(v1);
                    __nv_bfloat16 l0b = __float2bfloat16(v0 - __bfloat162float(h0b));
                    __nv_bfloat16 l1b = __float2bfloat16(v1 - __bfloat162float(h1b));
                    __nv_bfloat16* ox = (__nv_bfloat16*)ps.outA[e];
                    size_t pos = ((size_t)b*Hc + h)*Wc + wcol;
                    ox[pos*128 + oc]            = h0b;
                    ox[pos*128 + 64 + oc]       = l0b;
                    ox[(pos+1)*128 + oc]        = h1b;
                    ox[(pos+1)*128 + 64 + oc]   = l1b;
                } else {
                    float ao = d_aout[oc];
                    *(float2*)((float*)ps.outA[e] + base) = make_float2(ao*v0, ao*v1);
                }
            }
        }
    }
}

// ---------------- launch ----------------
extern "C" void kernel_launch(void* const* d_in, const int* in_sizes, int n_in,
                              void* d_out, int out_size){
    const float *x=nullptr, *a1=nullptr, *a2=nullptr, *W=nullptr;
    for (int i=0;i<n_in;i++){
        if (in_sizes[i]==TOTSZ) x=(const float*)d_in[i];
        else if (in_sizes[i]==WSZ) W=(const float*)d_in[i];
        else if (in_sizes[i]==8){ if(!a1) a1=(const float*)d_in[i]; else a2=(const float*)d_in[i]; }
    }
    float* out = (float*)d_out;

    __nv_bfloat16 *x0p,*x1p,*x2p;
    float *acc2,*acc3;
    cudaGetSymbolAddress((void**)&x0p,d_x0);
    cudaGetSymbolAddress((void**)&x1p,d_x1);
    cudaGetSymbolAddress((void**)&x2p,d_x2);
    cudaGetSymbolAddress((void**)&acc2,d_acc2);
    cudaGetSymbolAddress((void**)&acc3,d_acc3);

    const int smem3 = SM_IN_SZ + 2*3*64*272;
    const int smem2 = SM_IN_SZ + 2*2*64*272;
    const int smem1 = SM_IN_SZ + 2*1*64*272;
    cudaFuncSetAttribute(conv_mma_kernel<3>, cudaFuncAttributeMaxDynamicSharedMemorySize, smem3);
    cudaFuncSetAttribute(conv_mma_kernel<2>, cudaFuncAttributeMaxDynamicSharedMemorySize, smem2);
    cudaFuncSetAttribute(conv_mma_kernel<1>, cudaFuncAttributeMaxDynamicSharedMemorySize, smem1);

    scales_kernel<<<1, 64>>>(a1, a2);
    wprep_kernel<<<(NEDGE*9*Cc*Cc + 255)/256, 256>>>(W);
    inprep_kernel<<<dim3(Hc, Bc), 256>>>(x);

    // Pass A: x0 -> { W0 -> x1 (mode1), W1 -> acc2 (mode0), W3 -> acc3 (mode0) }
    PassSpec pa{};
    pa.l[0]=0; pa.mode[0]=1; pa.addin[0]=nullptr; pa.outA[0]=x1p;
    pa.l[1]=1; pa.mode[1]=0; pa.addin[1]=nullptr; pa.outA[1]=acc2;
    pa.l[2]=3; pa.mode[2]=0; pa.addin[2]=nullptr; pa.outA[2]=acc3;
    pa.in = x0p;
    conv_mma_kernel<3><<<dim3(8, Bc), NT, smem3>>>(pa);

    // Pass B: x1 -> { W2 + acc2 -> x2 (mode1), W4 + acc3 -> acc3 (mode0) }
    PassSpec pb{};
    pb.l[0]=2; pb.mode[0]=1; pb.addin[0]=acc2; pb.outA[0]=x2p;
    pb.l[1]=4; pb.mode[1]=0; pb.addin[1]=acc3; pb.outA[1]=acc3;
    pb.in = x1p;
    conv_mma_kernel<2><<<dim3(8, Bc), NT, smem2>>>(pb);

    // Pass C: x2 -> { W5 + acc3 -> out (mode2) }
    PassSpec pc{};
    pc.l[0]=5; pc.mode[0]=2; pc.addin[0]=acc3; pc.outA[0]=out;
    pc.in = x2p;
    conv_mma_kernel<1><<<dim3(8, Bc), NT, smem1>>>(pc);

    (void)out_size;
}

// round 9
// speedup vs baseline: 2.9037x; 1.1414x over previous
#include <cuda_runtime.h>
#include <cuda_bf16.h>
#include <cstdint>

#define Bc 128
#define Cc 64
#define Hc 32
#define Wc 32
#define NEDGE 6
#define TOTSZ (Bc*Cc*Hc*Wc)
#define WSZ   (NEDGE*Cc*Cc*9)

typedef unsigned int u32;

// ---------------- device scratch ----------------
// activations: [b][h][w][128] bf16, k=0..63 hi(ci), k=64..127 lo(ci)
__device__ __align__(16) __nv_bfloat16 d_x0[TOTSZ*2];
__device__ __align__(16) __nv_bfloat16 d_x1[TOTSZ*2];
__device__ __align__(16) __nv_bfloat16 d_x2[TOTSZ*2];
__device__ float d_acc2[TOTSZ];     // NCHW fp32
__device__ float d_acc3[TOTSZ];     // NCHW fp32
// weights: [l][s][oc][128] bf16, k=0..63 hi(ci), 64..127 lo(ci)
__device__ __align__(16) __nv_bfloat16 d_wm[NEDGE*9*Cc*128];
__device__ float d_ain[Cc], d_aout[Cc];

// ---------------- PTX helpers (baseline sm_80+ PTX only) ----------------
__device__ __forceinline__ u32 smem_u32(const void* p){
    u32 a; asm("{ .reg .u64 t; cvta.to.shared.u64 t, %1; cvt.u32.u64 %0, t; }":"=r"(a):"l"(p)); return a;
}
#define CP16(dst,src) asm volatile("cp.async.ca.shared.global [%0], [%1], 16;"::"r"(dst),"l"(src):"memory")
#define CPCOMMIT()    asm volatile("cp.async.commit_group;":::"memory")
#define CPWAIT1()     asm volatile("cp.async.wait_group 1;":::"memory")
#define CPWAIT0()     asm volatile("cp.async.wait_group 0;":::"memory")

#define LDSM4(r0,r1,r2,r3,addr) \
    asm volatile("ldmatrix.sync.aligned.m8n8.x4.shared.b16 {%0,%1,%2,%3}, [%4];" \
        : "=r"(r0),"=r"(r1),"=r"(r2),"=r"(r3) : "r"(addr))

#define MMA(c,a0,a1,a2,a3,b0,b1) \
    asm volatile("mma.sync.aligned.m16n8k16.row.col.f32.bf16.bf16.f32 " \
        "{%0,%1,%2,%3},{%4,%5,%6,%7},{%8,%9},{%0,%1,%2,%3};" \
        : "+f"((c)[0]),"+f"((c)[1]),"+f"((c)[2]),"+f"((c)[3]) \
        : "r"(a0),"r"(a1),"r"(a2),"r"(a3),"r"(b0),"r"(b1))

// ---------------- prep kernels ----------------
__global__ void scales_kernel(const float* __restrict__ a1, const float* __restrict__ a2){
    int c = threadIdx.x;
    if (c < Cc){
        float s1=0.f, s2=0.f;
        #pragma unroll
        for (int i=0;i<8;i++) if (c < 8*(i+1)) { s1+=a1[i]; s2+=a2[i]; }
        d_ain[c]=s1; d_aout[c]=s2;
    }
}

// W OIHW -> [l][s][oc][128] bf16 (hi|lo)
__global__ void wprep_kernel(const float* __restrict__ W){
    int idx = blockIdx.x*256 + threadIdx.x;
    if (idx >= NEDGE*9*Cc*Cc) return;
    int ci = idx & 63, t = idx >> 6;
    int oc = t & 63; t >>= 6;
    int s = t % 9, l = t / 9;
    float w = W[(((l*Cc + oc)*Cc + ci)*9) + s];
    __nv_bfloat16 hb = __float2bfloat16(w);
    __nv_bfloat16 lb = __float2bfloat16(w - __bfloat162float(hb));
    size_t base = (size_t)((l*9 + s)*Cc + oc) * 128;
    d_wm[base + ci]      = hb;
    d_wm[base + 64 + ci] = lb;
}

// x NCHW fp32 -> d_x0 [b][h][w][128] with a_in*relu and hi/lo split
__global__ void inprep_kernel(const float* __restrict__ x){
    __shared__ float tile[Cc][Wc+1];
    int b = blockIdx.y, h = blockIdx.x, t = threadIdx.x;
    int w = t & 31, cb = t >> 5;
    #pragma unroll
    for (int i=0;i<8;i++){
        int c = cb*8 + i;
        tile[c][w] = x[(((size_t)b*Cc + c)*Hc + h)*Wc + w];
    }
    __syncthreads();
    int w2 = t >> 3, cg = (t & 7) * 8;
    u32 hi[4], lo[4];
    #pragma unroll
    for (int i=0;i<4;i++){
        int c = cg + i*2;
        float v0 = d_ain[c]   * fmaxf(tile[c][w2],   0.f);
        float v1 = d_ain[c+1] * fmaxf(tile[c+1][w2], 0.f);
        __nv_bfloat16 h0b=__float2bfloat16(v0), h1b=__float2bfloat16(v1);
        __nv_bfloat16 l0b=__float2bfloat16(v0-__bfloat162float(h0b));
        __nv_bfloat16 l1b=__float2bfloat16(v1-__bfloat162float(h1b));
        hi[i]=(u32)__bfloat16_as_ushort(h0b)|((u32)__bfloat16_as_ushort(h1b)<<16);
        lo[i]=(u32)__bfloat16_as_ushort(l0b)|((u32)__bfloat16_as_ushort(l1b)<<16);
    }
    size_t pos = ((size_t)b*Hc + h)*Wc + w2;
    *(uint4*)(d_x0 + pos*128 + cg)      = make_uint4(hi[0],hi[1],hi[2],hi[3]);
    *(uint4*)(d_x0 + pos*128 + 64 + cg) = make_uint4(lo[0],lo[1],lo[2],lo[3]);
}

// ---------------- conv pass (mma.sync bf16, 256 threads, 2 CTAs/SM) ----------------
struct PassSpec {
    int l[3];
    int mode[3];            // 0: fp32 NCHW acc; 1: relu+split -> next d_x; 2: final NCHW out
    const float* addin[3];  // NCHW fp32 or null
    void* outA[3];
    const __nv_bfloat16* in;
};

// smem: input tile [204 pos][272B], then 2 weight bufs [Et*32 oc][272B]
#define SM_IN_SZ (204*272)
#define NT 256

template<int Et>
__global__ __launch_bounds__(NT, 2)
void conv_mma_kernel(PassSpec ps){
    extern __shared__ __align__(16) char smem[];
    const u32 sb  = smem_u32(smem);
    const int tid = threadIdx.x;
    const int lane = tid & 31, wrp = tid >> 5;
    const int wn = wrp & 3, wm = wrp >> 2;        // 4 n-rows x 2 m-groups
    const int band = blockIdx.x, b = blockIdx.y;
    const int och = blockIdx.z;                   // oc half: 0 -> oc 0..31, 1 -> 32..63
    const int h0 = band * 4;
    const int WBUF = Et*32*272;
    const u32 sbW = sb + SM_IN_SZ;

    // ---- stage input tile: 204 pos rows x 256B (+16B pad) ----
    for (int idx = tid; idx < 204*16; idx += NT){
        int p = idx >> 4, ch = idx & 15;
        int trow = p / 34, tcol = p - trow*34;
        int ih = h0 - 1 + trow, iw = tcol - 1;
        u32 dst = sb + p*272 + ch*16;
        if ((unsigned)ih < 32u && (unsigned)iw < 32u){
            const char* src = (const char*)(ps.in + ((size_t)((b*Hc + ih)*Wc + iw) << 7)) + ch*16;
            CP16(dst, src);
        } else {
            asm volatile("st.shared.v4.b32 [%0], {%1,%1,%1,%1};"::"r"(dst),"r"(0):"memory");
        }
    }
    // ---- stage weights (this CTA's 32-oc half) for tap 0 into buf 0 ----
    for (int idx = tid; idx < Et*512; idx += NT){
        int r = idx >> 4, ch = idx & 15;
        int e = r >> 5, rl = r & 31;
        u32 dst = sbW + r*272 + ch*16;
        const char* src = (const char*)d_wm + (((size_t)(ps.l[e]*9 + 0)*64 + och*32 + rl) << 8) + ch*16;
        CP16(dst, src);
    }
    CPCOMMIT();

    // ldmatrix lane patterns
    const int g = lane >> 3, lm = lane & 7;
    const u32 patB = (u32)(((g&2)?8:0) + lm)*272 + ((g&1)?16:0);
    const u32 patA = (u32)(((g&1)?8:0) + lm)*272 + ((g&2)?16:0);
    int Arow[Et];
    #pragma unroll
    for (int j = 0; j < Et; j++)
        Arow[j] = (wm*Et + j)*16*272;

    float acc[Et][4][4];
    #pragma unroll
    for (int j = 0; j < Et; j++)
        #pragma unroll
        for (int nt = 0; nt < 4; nt++)
            #pragma unroll
            for (int q = 0; q < 4; q++) acc[j][nt][q] = 0.f;

    #pragma unroll 1
    for (int tap = 0; tap < 9; tap++){
        if (tap + 1 < 9){
            int buf = (tap + 1) & 1;
            for (int idx = tid; idx < Et*512; idx += NT){
                int r = idx >> 4, ch = idx & 15;
                int e = r >> 5, rl = r & 31;
                u32 dst = sbW + buf*WBUF + r*272 + ch*16;
                const char* src = (const char*)d_wm + (((size_t)(ps.l[e]*9 + tap + 1)*64 + och*32 + rl) << 8) + ch*16;
                CP16(dst, src);
            }
            CPCOMMIT();
            CPWAIT1();
        } else {
            CPCOMMIT();
            CPWAIT0();
        }
        __syncthreads();

        const int ky = tap / 3, kx = tap - ky*3;
        const u32 pB = sb + (u32)((wn + ky)*34 + kx)*272 + patB;
        const u32 pA = sbW + (tap & 1)*WBUF + patA;

        // fragment-reuse inner loop: products share A_hi and B_hi fragments
        #pragma unroll
        for (int kk = 0; kk < 4; kk++){
            u32 bh0,bh1,bh2,bh3,bh4,bh5,bh6,bh7;
            u32 bl0,bl1,bl2,bl3,bl4,bl5,bl6,bl7;
            LDSM4(bh0,bh1,bh2,bh3, pB + 32*kk);
            LDSM4(bh4,bh5,bh6,bh7, pB + 32*kk + 16*272);
            LDSM4(bl0,bl1,bl2,bl3, pB + 128 + 32*kk);
            LDSM4(bl4,bl5,bl6,bl7, pB + 128 + 32*kk + 16*272);
            #pragma unroll
            for (int j = 0; j < Et; j++){
                u32 ah0,ah1,ah2,ah3, al0,al1,al2,al3;
                LDSM4(ah0,ah1,ah2,ah3, pA + Arow[j] + 32*kk);
                LDSM4(al0,al1,al2,al3, pA + Arow[j] + 128 + 32*kk);
                // A_hi x B_hi
                MMA(acc[j][0], ah0,ah1,ah2,ah3, bh0,bh1);
                MMA(acc[j][1], ah0,ah1,ah2,ah3, bh2,bh3);
                MMA(acc[j][2], ah0,ah1,ah2,ah3, bh4,bh5);
                MMA(acc[j][3], ah0,ah1,ah2,ah3, bh6,bh7);
                // A_lo x B_hi
                MMA(acc[j][0], al0,al1,al2,al3, bh0,bh1);
                MMA(acc[j][1], al0,al1,al2,al3, bh2,bh3);
                MMA(acc[j][2], al0,al1,al2,al3, bh4,bh5);
                MMA(acc[j][3], al0,al1,al2,al3, bh6,bh7);
                // A_hi x B_lo
                MMA(acc[j][0], ah0,ah1,ah2,ah3, bl0,bl1);
                MMA(acc[j][1], ah0,ah1,ah2,ah3, bl2,bl3);
                MMA(acc[j][2], ah0,ah1,ah2,ah3, bl4,bl5);
                MMA(acc[j][3], ah0,ah1,ah2,ah3, bl6,bl7);
            }
        }
        __syncthreads();
    }

    // ---------------- epilogue ----------------
    const int h = h0 + wn;
    #pragma unroll
    for (int j = 0; j < Et; j++){
        int t = wm*Et + j;
        int e = t >> 1;                              // 2 m-tiles per edge (32 oc)
        int ocb = och*32 + (t & 1)*16 + (lane >> 2);
        int mode = ps.mode[e];
        const float* add = ps.addin[e];
        #pragma unroll
        for (int nt = 0; nt < 4; nt++){
            int wcol = nt*8 + 2*(lane & 3);
            #pragma unroll
            for (int half = 0; half < 2; half++){
                int oc = ocb + half*8;
                float v0 = acc[j][nt][half*2 + 0];
                float v1 = acc[j][nt][half*2 + 1];
                size_t base = (((size_t)b*Cc + oc)*Hc + h)*Wc + wcol;
                if (add){
                    float2 a2 = *(const float2*)(add + base);
                    v0 += a2.x; v1 += a2.y;
                }
                if (mode == 0){
                    *(float2*)((float*)ps.outA[e] + base) = make_float2(v0, v1);
                } else if (mode == 1){
                    float ai = d_ain[oc], ao = d_aout[oc];
                    v0 = ai * fmaxf(ao * v0, 0.f);
                    v1 = ai * fmaxf(ao * v1, 0.f);
                    __nv_bfloat16 h0b = __float2bfloat16(v0);
                    __nv_bfloat16 h1b = __float2bfloat16(v1);
                    __nv_bfloat16 l0b = __float2bfloat16(v0 - __bfloat162float(h0b));
                    __nv_bfloat16 l1b = __float2bfloat16(v1 - __bfloat162float(h1b));
                    __nv_bfloat16* ox = (__nv_bfloat16*)ps.outA[e];
                    size_t pos = ((size_t)b*Hc + h)*Wc + wcol;
                    ox[pos*128 + oc]            = h0b;
                    ox[pos*128 + 64 + oc]       = l0b;
                    ox[(pos+1)*128 + oc]        = h1b;
                    ox[(pos+1)*128 + 64 + oc]   = l1b;
                } else {
                    float ao = d_aout[oc];
                    *(float2*)((float*)ps.outA[e] + base) = make_float2(ao*v0, ao*v1);
                }
            }
        }
    }
}

// ---------------- launch ----------------
extern "C" void kernel_launch(void* const* d_in, const int* in_sizes, int n_in,
                              void* d_out, int out_size){
    const float *x=nullptr, *a1=nullptr, *a2=nullptr, *W=nullptr;
    for (int i=0;i<n_in;i++){
        if (in_sizes[i]==TOTSZ) x=(const float*)d_in[i];
        else if (in_sizes[i]==WSZ) W=(const float*)d_in[i];
        else if (in_sizes[i]==8){ if(!a1) a1=(const float*)d_in[i]; else a2=(const float*)d_in[i]; }
    }
    float* out = (float*)d_out;

    __nv_bfloat16 *x0p,*x1p,*x2p;
    float *acc2,*acc3;
    cudaGetSymbolAddress((void**)&x0p,d_x0);
    cudaGetSymbolAddress((void**)&x1p,d_x1);
    cudaGetSymbolAddress((void**)&x2p,d_x2);
    cudaGetSymbolAddress((void**)&acc2,d_acc2);
    cudaGetSymbolAddress((void**)&acc3,d_acc3);

    const int smem3 = SM_IN_SZ + 2*3*32*272;   // 107712
    const int smem2 = SM_IN_SZ + 2*2*32*272;   //  90304
    const int smem1 = SM_IN_SZ + 2*1*32*272;   //  72896
    cudaFuncSetAttribute(conv_mma_kernel<3>, cudaFuncAttributeMaxDynamicSharedMemorySize, smem3);
    cudaFuncSetAttribute(conv_mma_kernel<2>, cudaFuncAttributeMaxDynamicSharedMemorySize, smem2);
    cudaFuncSetAttribute(conv_mma_kernel<1>, cudaFuncAttributeMaxDynamicSharedMemorySize, smem1);

    scales_kernel<<<1, 64>>>(a1, a2);
    wprep_kernel<<<(NEDGE*9*Cc*Cc + 255)/256, 256>>>(W);
    inprep_kernel<<<dim3(Hc, Bc), 256>>>(x);

    // Pass A: x0 -> { W0 -> x1 (mode1), W1 -> acc2 (mode0), W3 -> acc3 (mode0) }
    PassSpec pa{};
    pa.l[0]=0; pa.mode[0]=1; pa.addin[0]=nullptr; pa.outA[0]=x1p;
    pa.l[1]=1; pa.mode[1]=0; pa.addin[1]=nullptr; pa.outA[1]=acc2;
    pa.l[2]=3; pa.mode[2]=0; pa.addin[2]=nullptr; pa.outA[2]=acc3;
    pa.in = x0p;
    conv_mma_kernel<3><<<dim3(8, Bc, 2), NT, smem3>>>(pa);

    // Pass B: x1 -> { W2 + acc2 -> x2 (mode1), W4 + acc3 -> acc3 (mode0) }
    PassSpec pb{};
    pb.l[0]=2; pb.mode[0]=1; pb.addin[0]=acc2; pb.outA[0]=x2p;
    pb.l[1]=4; pb.mode[1]=0; pb.addin[1]=acc3; pb.outA[1]=acc3;
    pb.in = x1p;
    conv_mma_kernel<2><<<dim3(8, Bc, 2), NT, smem2>>>(pb);

    // Pass C: x2 -> { W5 + acc3 -> out (mode2) }
    PassSpec pc{};
    pc.l[0]=5; pc.mode[0]=2; pc.addin[0]=acc3; pc.outA[0]=out;
    pc.in = x2p;
    conv_mma_kernel<1><<<dim3(8, Bc, 2), NT, smem1>>>(pc);

    (void)out_size;
}

// round 10
// speedup vs baseline: 3.5703x; 1.2295x over previous
#include <cuda_runtime.h>
#include <cuda_fp16.h>
#include <cstdint>

#define Bc 128
#define Cc 64
#define Hc 32
#define Wc 32
#define NEDGE 6
#define TOTSZ (Bc*Cc*Hc*Wc)
#define WSZ   (NEDGE*Cc*Cc*9)

typedef unsigned int u32;

// ---------------- device scratch ----------------
// activations: [b][h][w][128] fp16, k=0..63 hi(ci), k=64..127 lo(ci)
__device__ __align__(16) __half d_x0[TOTSZ*2];
__device__ __align__(16) __half d_x1[TOTSZ*2];
__device__ __align__(16) __half d_x2[TOTSZ*2];
__device__ float d_acc2[TOTSZ];     // NCHW fp32
__device__ float d_acc3[TOTSZ];     // NCHW fp32
// weights: [l][s][oc][64] fp16 single-limb
__device__ __align__(16) __half d_wm[NEDGE*9*Cc*64];
__device__ float d_ain[Cc], d_aout[Cc];

// ---------------- PTX helpers (baseline sm_80+ PTX only) ----------------
__device__ __forceinline__ u32 smem_u32(const void* p){
    u32 a; asm("{ .reg .u64 t; cvta.to.shared.u64 t, %1; cvt.u32.u64 %0, t; }":"=r"(a):"l"(p)); return a;
}
#define CP16(dst,src) asm volatile("cp.async.ca.shared.global [%0], [%1], 16;"::"r"(dst),"l"(src):"memory")
#define CPCOMMIT()    asm volatile("cp.async.commit_group;":::"memory")
#define CPWAIT1()     asm volatile("cp.async.wait_group 1;":::"memory")
#define CPWAIT0()     asm volatile("cp.async.wait_group 0;":::"memory")

#define LDSM4(r0,r1,r2,r3,addr) \
    asm volatile("ldmatrix.sync.aligned.m8n8.x4.shared.b16 {%0,%1,%2,%3}, [%4];" \
        : "=r"(r0),"=r"(r1),"=r"(r2),"=r"(r3) : "r"(addr))

#define MMAH(c,a0,a1,a2,a3,b0,b1) \
    asm volatile("mma.sync.aligned.m16n8k16.row.col.f32.f16.f16.f32 " \
        "{%0,%1,%2,%3},{%4,%5,%6,%7},{%8,%9},{%0,%1,%2,%3};" \
        : "+f"((c)[0]),"+f"((c)[1]),"+f"((c)[2]),"+f"((c)[3]) \
        : "r"(a0),"r"(a1),"r"(a2),"r"(a3),"r"(b0),"r"(b1))

// ---------------- prep kernels ----------------
__global__ void scales_kernel(const float* __restrict__ a1, const float* __restrict__ a2){
    int c = threadIdx.x;
    if (c < Cc){
        float s1=0.f, s2=0.f;
        #pragma unroll
        for (int i=0;i<8;i++) if (c < 8*(i+1)) { s1+=a1[i]; s2+=a2[i]; }
        d_ain[c]=s1; d_aout[c]=s2;
    }
}

// W OIHW -> [l][s][oc][64] fp16
__global__ void wprep_kernel(const float* __restrict__ W){
    int idx = blockIdx.x*256 + threadIdx.x;
    if (idx >= NEDGE*9*Cc*Cc) return;
    int ci = idx & 63, t = idx >> 6;
    int oc = t & 63; t >>= 6;
    int s = t % 9, l = t / 9;
    float w = W[(((l*Cc + oc)*Cc + ci)*9) + s];
    d_wm[(size_t)((l*9 + s)*Cc + oc) * 64 + ci] = __float2half_rn(w);
}

// x NCHW fp32 -> d_x0 [b][h][w][128] with a_in*relu, fp16 hi/lo split
__global__ void inprep_kernel(const float* __restrict__ x){
    __shared__ float tile[Cc][Wc+1];
    int b = blockIdx.y, h = blockIdx.x, t = threadIdx.x;
    int w = t & 31, cb = t >> 5;
    #pragma unroll
    for (int i=0;i<8;i++){
        int c = cb*8 + i;
        tile[c][w] = x[(((size_t)b*Cc + c)*Hc + h)*Wc + w];
    }
    __syncthreads();
    int w2 = t >> 3, cg = (t & 7) * 8;
    u32 hi[4], lo[4];
    #pragma unroll
    for (int i=0;i<4;i++){
        int c = cg + i*2;
        float v0 = d_ain[c]   * fmaxf(tile[c][w2],   0.f);
        float v1 = d_ain[c+1] * fmaxf(tile[c+1][w2], 0.f);
        __half h0b=__float2half_rn(v0), h1b=__float2half_rn(v1);
        __half l0b=__float2half_rn(v0-__half2float(h0b));
        __half l1b=__float2half_rn(v1-__half2float(h1b));
        hi[i]=(u32)__half_as_ushort(h0b)|((u32)__half_as_ushort(h1b)<<16);
        lo[i]=(u32)__half_as_ushort(l0b)|((u32)__half_as_ushort(l1b)<<16);
    }
    size_t pos = ((size_t)b*Hc + h)*Wc + w2;
    *(uint4*)(d_x0 + pos*128 + cg)      = make_uint4(hi[0],hi[1],hi[2],hi[3]);
    *(uint4*)(d_x0 + pos*128 + 64 + cg) = make_uint4(lo[0],lo[1],lo[2],lo[3]);
}

// ---------------- conv pass (mma.sync f16, 256 threads, 2 CTAs/SM) ----------------
struct PassSpec {
    int l[3];
    int mode[3];            // 0: fp32 NCHW acc; 1: relu+split -> next d_x; 2: final NCHW out
    const float* addin[3];  // NCHW fp32 or null
    void* outA[3];
    const __half* in;
};

// smem: input tile [204 pos][272B], then 3 weight bufs [Et*32 oc][144B]
#define SM_IN_SZ (204*272)
#define NT 256

template<int Et>
__global__ __launch_bounds__(NT, 2)
void conv_mma_kernel(PassSpec ps){
    extern __shared__ __align__(16) char smem[];
    const u32 sb  = smem_u32(smem);
    const int tid = threadIdx.x;
    const int lane = tid & 31, wrp = tid >> 5;
    const int wn = wrp & 3, wm = wrp >> 2;        // 4 n-rows x 2 m-groups
    const int band = blockIdx.x, b = blockIdx.y;
    const int och = blockIdx.z;                   // oc half
    const int h0 = band * 4;
    const int WBUF = Et*32*144;
    const u32 sbW = sb + SM_IN_SZ;

    // ---- stage input tile: 204 pos rows x 256B (+16B pad) ----
    for (int idx = tid; idx < 204*16; idx += NT){
        int p = idx >> 4, ch = idx & 15;
        int trow = p / 34, tcol = p - trow*34;
        int ih = h0 - 1 + trow, iw = tcol - 1;
        u32 dst = sb + p*272 + ch*16;
        if ((unsigned)ih < 32u && (unsigned)iw < 32u){
            const char* src = (const char*)(ps.in + ((size_t)((b*Hc + ih)*Wc + iw) << 7)) + ch*16;
            CP16(dst, src);
        } else {
            asm volatile("st.shared.v4.b32 [%0], {%1,%1,%1,%1};"::"r"(dst),"r"(0):"memory");
        }
    }
    // ---- stage weights (this CTA's 32-oc half) tap 0 into buf 0: rows 128B ----
    for (int idx = tid; idx < Et*256; idx += NT){
        int r = idx >> 3, ch = idx & 7;
        int e = r >> 5, rl = r & 31;
        u32 dst = sbW + r*144 + ch*16;
        const char* src = (const char*)d_wm + (((size_t)(ps.l[e]*9 + 0)*64 + och*32 + rl) << 7) + ch*16;
        CP16(dst, src);
    }
    CPCOMMIT();

    // ldmatrix lane patterns
    const int g = lane >> 3, lm = lane & 7;
    const u32 patB = (u32)(((g&2)?8:0) + lm)*272 + ((g&1)?16:0);
    const u32 patA = (u32)(((g&1)?8:0) + lm)*144 + ((g&2)?16:0);
    int Arow[Et];
    #pragma unroll
    for (int j = 0; j < Et; j++)
        Arow[j] = (wm*Et + j)*16*144;

    float acc[Et][4][4];
    #pragma unroll
    for (int j = 0; j < Et; j++)
        #pragma unroll
        for (int nt = 0; nt < 4; nt++)
            #pragma unroll
            for (int q = 0; q < 4; q++) acc[j][nt][q] = 0.f;

    #pragma unroll 1
    for (int tap = 0; tap < 9; tap++){
        if (tap + 1 < 9){
            int buf = (tap + 1) % 3;
            for (int idx = tid; idx < Et*256; idx += NT){
                int r = idx >> 3, ch = idx & 7;
                int e = r >> 5, rl = r & 31;
                u32 dst = sbW + buf*WBUF + r*144 + ch*16;
                const char* src = (const char*)d_wm + (((size_t)(ps.l[e]*9 + tap + 1)*64 + och*32 + rl) << 7) + ch*16;
                CP16(dst, src);
            }
            CPCOMMIT();
            CPWAIT1();
        } else {
            CPWAIT0();
        }
        __syncthreads();   // single barrier per tap (triple-buffered weights)

        const int ky = tap / 3, kx = tap - ky*3;
        const u32 pB = sb + (u32)((wn + ky)*34 + kx)*272 + patB;
        const u32 pA = sbW + (tap % 3)*WBUF + patA;

        #pragma unroll
        for (int kk = 0; kk < 4; kk++){
            u32 bh0,bh1,bh2,bh3,bh4,bh5,bh6,bh7;
            u32 bl0,bl1,bl2,bl3,bl4,bl5,bl6,bl7;
            LDSM4(bh0,bh1,bh2,bh3, pB + 32*kk);
            LDSM4(bh4,bh5,bh6,bh7, pB + 32*kk + 16*272);
            LDSM4(bl0,bl1,bl2,bl3, pB + 128 + 32*kk);
            LDSM4(bl4,bl5,bl6,bl7, pB + 128 + 32*kk + 16*272);
            #pragma unroll
            for (int j = 0; j < Et; j++){
                u32 a0,a1,a2,a3;
                LDSM4(a0,a1,a2,a3, pA + Arow[j] + 32*kk);
                // w x x_hi
                MMAH(acc[j][0], a0,a1,a2,a3, bh0,bh1);
                MMAH(acc[j][1], a0,a1,a2,a3, bh2,bh3);
                MMAH(acc[j][2], a0,a1,a2,a3, bh4,bh5);
                MMAH(acc[j][3], a0,a1,a2,a3, bh6,bh7);
                // w x x_lo
                MMAH(acc[j][0], a0,a1,a2,a3, bl0,bl1);
                MMAH(acc[j][1], a0,a1,a2,a3, bl2,bl3);
                MMAH(acc[j][2], a0,a1,a2,a3, bl4,bl5);
                MMAH(acc[j][3], a0,a1,a2,a3, bl6,bl7);
            }
        }
    }

    // ---------------- epilogue ----------------
    const int h = h0 + wn;
    #pragma unroll
    for (int j = 0; j < Et; j++){
        int t = wm*Et + j;
        int e = t >> 1;                              // 2 m-tiles per edge (32 oc)
        int ocb = och*32 + (t & 1)*16 + (lane >> 2);
        int mode = ps.mode[e];
        const float* add = ps.addin[e];
        #pragma unroll
        for (int nt = 0; nt < 4; nt++){
            int wcol = nt*8 + 2*(lane & 3);
            #pragma unroll
            for (int half = 0; half < 2; half++){
                int oc = ocb + half*8;
                float v0 = acc[j][nt][half*2 + 0];
                float v1 = acc[j][nt][half*2 + 1];
                size_t base = (((size_t)b*Cc + oc)*Hc + h)*Wc + wcol;
                if (add){
                    float2 a2 = *(const float2*)(add + base);
                    v0 += a2.x; v1 += a2.y;
                }
                if (mode == 0){
                    *(float2*)((float*)ps.outA[e] + base) = make_float2(v0, v1);
                } else if (mode == 1){
                    float ai = d_ain[oc], ao = d_aout[oc];
                    v0 = ai * fmaxf(ao * v0, 0.f);
                    v1 = ai * fmaxf(ao * v1, 0.f);
                    __half h0b = __float2half_rn(v0);
                    __half h1b = __float2half_rn(v1);
                    __half l0b = __float2half_rn(v0 - __half2float(h0b));
                    __half l1b = __float2half_rn(v1 - __half2float(h1b));
                    __half* ox = (__half*)ps.outA[e];
                    size_t pos = ((size_t)b*Hc + h)*Wc + wcol;
                    ox[pos*128 + oc]            = h0b;
                    ox[pos*128 + 64 + oc]       = l0b;
                    ox[(pos+1)*128 + oc]        = h1b;
                    ox[(pos+1)*128 + 64 + oc]   = l1b;
                } else {
                    float ao = d_aout[oc];
                    *(float2*)((float*)ps.outA[e] + base) = make_float2(ao*v0, ao*v1);
                }
            }
        }
    }
}

// ---------------- launch ----------------
extern "C" void kernel_launch(void* const* d_in, const int* in_sizes, int n_in,
                              void* d_out, int out_size){
    const float *x=nullptr, *a1=nullptr, *a2=nullptr, *W=nullptr;
    for (int i=0;i<n_in;i++){
        if (in_sizes[i]==TOTSZ) x=(const float*)d_in[i];
        else if (in_sizes[i]==WSZ) W=(const float*)d_in[i];
        else if (in_sizes[i]==8){ if(!a1) a1=(const float*)d_in[i]; else a2=(const float*)d_in[i]; }
    }
    float* out = (float*)d_out;

    __half *x0p,*x1p,*x2p;
    float *acc2,*acc3;
    cudaGetSymbolAddress((void**)&x0p,d_x0);
    cudaGetSymbolAddress((void**)&x1p,d_x1);
    cudaGetSymbolAddress((void**)&x2p,d_x2);
    cudaGetSymbolAddress((void**)&acc2,d_acc2);
    cudaGetSymbolAddress((void**)&acc3,d_acc3);

    const int smem3 = SM_IN_SZ + 3*3*32*144;   // 96960
    const int smem2 = SM_IN_SZ + 3*2*32*144;   // 83136
    const int smem1 = SM_IN_SZ + 3*1*32*144;   // 69312
    cudaFuncSetAttribute(conv_mma_kernel<3>, cudaFuncAttributeMaxDynamicSharedMemorySize, smem3);
    cudaFuncSetAttribute(conv_mma_kernel<2>, cudaFuncAttributeMaxDynamicSharedMemorySize, smem2);
    cudaFuncSetAttribute(conv_mma_kernel<1>, cudaFuncAttributeMaxDynamicSharedMemorySize, smem1);

    scales_kernel<<<1, 64>>>(a1, a2);
    wprep_kernel<<<(NEDGE*9*Cc*Cc + 255)/256, 256>>>(W);
    inprep_kernel<<<dim3(Hc, Bc), 256>>>(x);

    // Pass A: x0 -> { W0 -> x1 (mode1), W1 -> acc2 (mode0), W3 -> acc3 (mode0) }
    PassSpec pa{};
    pa.l[0]=0; pa.mode[0]=1; pa.addin[0]=nullptr; pa.outA[0]=x1p;
    pa.l[1]=1; pa.mode[1]=0; pa.addin[1]=nullptr; pa.outA[1]=acc2;
    pa.l[2]=3; pa.mode[2]=0; pa.addin[2]=nullptr; pa.outA[2]=acc3;
    pa.in = x0p;
    conv_mma_kernel<3><<<dim3(8, Bc, 2), NT, smem3>>>(pa);

    // Pass B: x1 -> { W2 + acc2 -> x2 (mode1), W4 + acc3 -> acc3 (mode0) }
    PassSpec pb{};
    pb.l[0]=2; pb.mode[0]=1; pb.addin[0]=acc2; pb.outA[0]=x2p;
    pb.l[1]=4; pb.mode[1]=0; pb.addin[1]=acc3; pb.outA[1]=acc3;
    pb.in = x1p;
    conv_mma_kernel<2><<<dim3(8, Bc, 2), NT, smem2>>>(pb);

    // Pass C: x2 -> { W5 + acc3 -> out (mode2) }
    PassSpec pc{};
    pc.l[0]=5; pc.mode[0]=2; pc.addin[0]=acc3; pc.outA[0]=out;
    pc.in = x2p;
    conv_mma_kernel<1><<<dim3(8, Bc, 2), NT, smem1>>>(pc);

    (void)out_size;
}

// round 11
// speedup vs baseline: 5.1332x; 1.4378x over previous
#include <cuda_runtime.h>
#include <cuda_fp16.h>
#include <cstdint>

#define Bc 128
#define Cc 64
#define Hc 32
#define Wc 32
#define NEDGE 6
#define TOTSZ (Bc*Cc*Hc*Wc)
#define WSZ   (NEDGE*Cc*Cc*9)

typedef unsigned int u32;

// ---------------- device scratch ----------------
// activations: [b][h][w][64] fp16 (single limb)
__device__ __align__(16) __half d_x0[TOTSZ];
__device__ __align__(16) __half d_x1[TOTSZ];
__device__ __align__(16) __half d_x2[TOTSZ];
__device__ float d_acc2[TOTSZ];     // NCHW fp32
__device__ float d_acc3[TOTSZ];     // NCHW fp32
// weights: [l][s][oc][64] fp16
__device__ __align__(16) __half d_wm[NEDGE*9*Cc*64];
__device__ float d_ain[Cc], d_aout[Cc];

// ---------------- PTX helpers (baseline sm_80+ PTX only) ----------------
__device__ __forceinline__ u32 smem_u32(const void* p){
    u32 a; asm("{ .reg .u64 t; cvta.to.shared.u64 t, %1; cvt.u32.u64 %0, t; }":"=r"(a):"l"(p)); return a;
}
#define CP16(dst,src) asm volatile("cp.async.ca.shared.global [%0], [%1], 16;"::"r"(dst),"l"(src):"memory")
#define CPCOMMIT()    asm volatile("cp.async.commit_group;":::"memory")
#define CPWAIT1()     asm volatile("cp.async.wait_group 1;":::"memory")
#define CPWAIT0()     asm volatile("cp.async.wait_group 0;":::"memory")

#define LDSM4(r0,r1,r2,r3,addr) \
    asm volatile("ldmatrix.sync.aligned.m8n8.x4.shared.b16 {%0,%1,%2,%3}, [%4];" \
        : "=r"(r0),"=r"(r1),"=r"(r2),"=r"(r3) : "r"(addr))

#define MMAH(c,a0,a1,a2,a3,b0,b1) \
    asm volatile("mma.sync.aligned.m16n8k16.row.col.f32.f16.f16.f32 " \
        "{%0,%1,%2,%3},{%4,%5,%6,%7},{%8,%9},{%0,%1,%2,%3};" \
        : "+f"((c)[0]),"+f"((c)[1]),"+f"((c)[2]),"+f"((c)[3]) \
        : "r"(a0),"r"(a1),"r"(a2),"r"(a3),"r"(b0),"r"(b1))

// ---------------- prep kernels ----------------
__global__ void scales_kernel(const float* __restrict__ a1, const float* __restrict__ a2){
    int c = threadIdx.x;
    if (c < Cc){
        float s1=0.f, s2=0.f;
        #pragma unroll
        for (int i=0;i<8;i++) if (c < 8*(i+1)) { s1+=a1[i]; s2+=a2[i]; }
        d_ain[c]=s1; d_aout[c]=s2;
    }
}

// W OIHW -> [l][s][oc][64] fp16
__global__ void wprep_kernel(const float* __restrict__ W){
    int idx = blockIdx.x*256 + threadIdx.x;
    if (idx >= NEDGE*9*Cc*Cc) return;
    int ci = idx & 63, t = idx >> 6;
    int oc = t & 63; t >>= 6;
    int s = t % 9, l = t / 9;
    float w = W[(((l*Cc + oc)*Cc + ci)*9) + s];
    d_wm[(size_t)((l*9 + s)*Cc + oc) * 64 + ci] = __float2half_rn(w);
}

// x NCHW fp32 -> d_x0 [b][h][w][64] with a_in*relu, fp16 round
__global__ void inprep_kernel(const float* __restrict__ x){
    __shared__ float tile[Cc][Wc+1];
    int b = blockIdx.y, h = blockIdx.x, t = threadIdx.x;
    int w = t & 31, cb = t >> 5;
    #pragma unroll
    for (int i=0;i<8;i++){
        int c = cb*8 + i;
        tile[c][w] = x[(((size_t)b*Cc + c)*Hc + h)*Wc + w];
    }
    __syncthreads();
    int w2 = t >> 3, cg = (t & 7) * 8;
    u32 hi[4];
    #pragma unroll
    for (int i=0;i<4;i++){
        int c = cg + i*2;
        float v0 = d_ain[c]   * fmaxf(tile[c][w2],   0.f);
        float v1 = d_ain[c+1] * fmaxf(tile[c+1][w2], 0.f);
        hi[i]=(u32)__half_as_ushort(__float2half_rn(v0))
             |((u32)__half_as_ushort(__float2half_rn(v1))<<16);
    }
    size_t pos = ((size_t)b*Hc + h)*Wc + w2;
    *(uint4*)(d_x0 + pos*64 + cg) = make_uint4(hi[0],hi[1],hi[2],hi[3]);
}

// ---------------- conv pass (mma.sync f16, 256 threads, 2 CTAs/SM) ----------------
struct PassSpec {
    int l[3];
    int mode[3];            // 0: fp32 NCHW acc; 1: relu -> next d_x fp16; 2: final NCHW out
    const float* addin[3];  // NCHW fp32 or null
    void* outA[3];
    const __half* in;
};

// smem: input tile [204 pos][144B], then 3 weight bufs [Et*32 oc][144B]
#define SM_IN_SZ (204*144)
#define NT 256

template<int Et>
__global__ __launch_bounds__(NT, 2)
void conv_mma_kernel(PassSpec ps){
    extern __shared__ __align__(16) char smem[];
    const u32 sb  = smem_u32(smem);
    const int tid = threadIdx.x;
    const int lane = tid & 31, wrp = tid >> 5;
    const int wn = wrp & 3, wm = wrp >> 2;        // 4 n-rows x 2 m-groups
    const int band = blockIdx.x, b = blockIdx.y;
    const int och = blockIdx.z;                   // oc half
    const int h0 = band * 4;
    const int WBUF = Et*32*144;
    const u32 sbW = sb + SM_IN_SZ;

    // ---- stage input tile: 204 pos rows x 128B (+16B pad) ----
    for (int idx = tid; idx < 204*8; idx += NT){
        int p = idx >> 3, ch = idx & 7;
        int trow = p / 34, tcol = p - trow*34;
        int ih = h0 - 1 + trow, iw = tcol - 1;
        u32 dst = sb + p*144 + ch*16;
        if ((unsigned)ih < 32u && (unsigned)iw < 32u){
            const char* src = (const char*)(ps.in + ((size_t)((b*Hc + ih)*Wc + iw) << 6)) + ch*16;
            CP16(dst, src);
        } else {
            asm volatile("st.shared.v4.b32 [%0], {%1,%1,%1,%1};"::"r"(dst),"r"(0):"memory");
        }
    }
    // ---- stage weights (this CTA's 32-oc half) tap 0 into buf 0 ----
    for (int idx = tid; idx < Et*256; idx += NT){
        int r = idx >> 3, ch = idx & 7;
        int e = r >> 5, rl = r & 31;
        u32 dst = sbW + r*144 + ch*16;
        const char* src = (const char*)d_wm + (((size_t)(ps.l[e]*9 + 0)*64 + och*32 + rl) << 7) + ch*16;
        CP16(dst, src);
    }
    CPCOMMIT();

    // ldmatrix lane patterns
    const int g = lane >> 3, lm = lane & 7;
    const u32 patB = (u32)(((g&2)?8:0) + lm)*144 + ((g&1)?16:0);
    const u32 patA = (u32)(((g&1)?8:0) + lm)*144 + ((g&2)?16:0);
    int Arow[Et];
    #pragma unroll
    for (int j = 0; j < Et; j++)
        Arow[j] = (wm*Et + j)*16*144;

    float acc[Et][4][4];
    #pragma unroll
    for (int j = 0; j < Et; j++)
        #pragma unroll
        for (int nt = 0; nt < 4; nt++)
            #pragma unroll
            for (int q = 0; q < 4; q++) acc[j][nt][q] = 0.f;

    #pragma unroll 1
    for (int tap = 0; tap < 9; tap++){
        if (tap + 1 < 9){
            int buf = (tap + 1) % 3;
            for (int idx = tid; idx < Et*256; idx += NT){
                int r = idx >> 3, ch = idx & 7;
                int e = r >> 5, rl = r & 31;
                u32 dst = sbW + buf*WBUF + r*144 + ch*16;
                const char* src = (const char*)d_wm + (((size_t)(ps.l[e]*9 + tap + 1)*64 + och*32 + rl) << 7) + ch*16;
                CP16(dst, src);
            }
            CPCOMMIT();
            CPWAIT1();
        } else {
            CPWAIT0();
        }
        __syncthreads();   // single barrier per tap (triple-buffered weights)

        const int ky = tap / 3, kx = tap - ky*3;
        const u32 pB = sb + (u32)((wn + ky)*34 + kx)*144 + patB;
        const u32 pA = sbW + (tap % 3)*WBUF + patA;

        #pragma unroll
        for (int kk = 0; kk < 4; kk++){
            u32 b0,b1,b2,b3,b4,b5,b6,b7;
            LDSM4(b0,b1,b2,b3, pB + 32*kk);
            LDSM4(b4,b5,b6,b7, pB + 32*kk + 16*144);
            #pragma unroll
            for (int j = 0; j < Et; j++){
                u32 a0,a1,a2,a3;
                LDSM4(a0,a1,a2,a3, pA + Arow[j] + 32*kk);
                MMAH(acc[j][0], a0,a1,a2,a3, b0,b1);
                MMAH(acc[j][1], a0,a1,a2,a3, b2,b3);
                MMAH(acc[j][2], a0,a1,a2,a3, b4,b5);
                MMAH(acc[j][3], a0,a1,a2,a3, b6,b7);
            }
        }
    }

    // ---------------- epilogue ----------------
    const int h = h0 + wn;
    #pragma unroll
    for (int j = 0; j < Et; j++){
        int t = wm*Et + j;
        int e = t >> 1;                              // 2 m-tiles per edge (32 oc)
        int ocb = och*32 + (t & 1)*16 + (lane >> 2);
        int mode = ps.mode[e];
        const float* add = ps.addin[e];
        #pragma unroll
        for (int nt = 0; nt < 4; nt++){
            int wcol = nt*8 + 2*(lane & 3);
            #pragma unroll
            for (int half = 0; half < 2; half++){
                int oc = ocb + half*8;
                float v0 = acc[j][nt][half*2 + 0];
                float v1 = acc[j][nt][half*2 + 1];
                size_t base = (((size_t)b*Cc + oc)*Hc + h)*Wc + wcol;
                if (add){
                    float2 a2 = *(const float2*)(add + base);
                    v0 += a2.x; v1 += a2.y;
                }
                if (mode == 0){
                    *(float2*)((float*)ps.outA[e] + base) = make_float2(v0, v1);
                } else if (mode == 1){
                    float ai = d_ain[oc], ao = d_aout[oc];
                    v0 = ai * fmaxf(ao * v0, 0.f);
                    v1 = ai * fmaxf(ao * v1, 0.f);
                    __half* ox = (__half*)ps.outA[e];
                    size_t pos = ((size_t)b*Hc + h)*Wc + wcol;
                    ox[pos*64 + oc]     = __float2half_rn(v0);
                    ox[(pos+1)*64 + oc] = __float2half_rn(v1);
                } else {
                    float ao = d_aout[oc];
                    *(float2*)((float*)ps.outA[e] + base) = make_float2(ao*v0, ao*v1);
                }
            }
        }
    }
}

// ---------------- launch ----------------
extern "C" void kernel_launch(void* const* d_in, const int* in_sizes, int n_in,
                              void* d_out, int out_size){
    const float *x=nullptr, *a1=nullptr, *a2=nullptr, *W=nullptr;
    for (int i=0;i<n_in;i++){
        if (in_sizes[i]==TOTSZ) x=(const float*)d_in[i];
        else if (in_sizes[i]==WSZ) W=(const float*)d_in[i];
        else if (in_sizes[i]==8){ if(!a1) a1=(const float*)d_in[i]; else a2=(const float*)d_in[i]; }
    }
    float* out = (float*)d_out;

    __half *x0p,*x1p,*x2p;
    float *acc2,*acc3;
    cudaGetSymbolAddress((void**)&x0p,d_x0);
    cudaGetSymbolAddress((void**)&x1p,d_x1);
    cudaGetSymbolAddress((void**)&x2p,d_x2);
    cudaGetSymbolAddress((void**)&acc2,d_acc2);
    cudaGetSymbolAddress((void**)&acc3,d_acc3);

    const int smem3 = SM_IN_SZ + 3*3*32*144;   // 70848
    const int smem2 = SM_IN_SZ + 3*2*32*144;   // 57024
    const int smem1 = SM_IN_SZ + 3*1*32*144;   // 43200
    cudaFuncSetAttribute(conv_mma_kernel<3>, cudaFuncAttributeMaxDynamicSharedMemorySize, smem3);
    cudaFuncSetAttribute(conv_mma_kernel<2>, cudaFuncAttributeMaxDynamicSharedMemorySize, smem2);
    cudaFuncSetAttribute(conv_mma_kernel<1>, cudaFuncAttributeMaxDynamicSharedMemorySize, smem1);

    scales_kernel<<<1, 64>>>(a1, a2);
    wprep_kernel<<<(NEDGE*9*Cc*Cc + 255)/256, 256>>>(W);
    inprep_kernel<<<dim3(Hc, Bc), 256>>>(x);

    // Pass A: x0 -> { W0 -> x1 (mode1), W1 -> acc2 (mode0), W3 -> acc3 (mode0) }
    PassSpec pa{};
    pa.l[0]=0; pa.mode[0]=1; pa.addin[0]=nullptr; pa.outA[0]=x1p;
    pa.l[1]=1; pa.mode[1]=0; pa.addin[1]=nullptr; pa.outA[1]=acc2;
    pa.l[2]=3; pa.mode[2]=0; pa.addin[2]=nullptr; pa.outA[2]=acc3;
    pa.in = x0p;
    conv_mma_kernel<3><<<dim3(8, Bc, 2), NT, smem3>>>(pa);

    // Pass B: x1 -> { W2 + acc2 -> x2 (mode1), W4 + acc3 -> acc3 (mode0) }
    PassSpec pb{};
    pb.l[0]=2; pb.mode[0]=1; pb.addin[0]=acc2; pb.outA[0]=x2p;
    pb.l[1]=4; pb.mode[1]=0; pb.addin[1]=acc3; pb.outA[1]=acc3;
    pb.in = x1p;
    conv_mma_kernel<2><<<dim3(8, Bc, 2), NT, smem2>>>(pb);

    // Pass C: x2 -> { W5 + acc3 -> out (mode2) }
    PassSpec pc{};
    pc.l[0]=5; pc.mode[0]=2; pc.addin[0]=acc3; pc.outA[0]=out;
    pc.in = x2p;
    conv_mma_kernel<1><<<dim3(8, Bc, 2), NT, smem1>>>(pc);

    (void)out_size;
}